// round 7
// baseline (speedup 1.0000x reference)
#include <cuda_runtime.h>
#include <cstdint>

#define NMAX    50048
#define EMAX    800000
#define ETOTMAX (NMAX + EMAX)
#define NBLKMAX 256

// ------------------------- scratch (device globals) -------------------------
__device__ __align__(16) float g_xl1[NMAX * 128];
__device__ __align__(16) float g_xr1[NMAX * 128];
__device__ __align__(16) float g_h1[NMAX * 128];
__device__ __align__(16) float g_xl2[NMAX * 64];
__device__ __align__(16) float g_xr2[NMAX * 64];
__device__ __align__(16) float g_h2[NMAX * 64];
__device__ __align__(16) int   g_deg[NMAX];
__device__ __align__(16) int   g_pre[NMAX];
__device__ __align__(16) int   g_bsum[NBLKMAX];
__device__ __align__(16) int   g_rowptr[NMAX + 1];
__device__ __align__(16) int   g_cursor[NMAX];
__device__ __align__(16) int   g_esrc[ETOTMAX];

// ------------------------- helpers -------------------------
__device__ __forceinline__ float elu1(float v) { return v > 0.f ? v : expm1f(v); }

__device__ __forceinline__ uint32_t f2tf32(float x) {
    uint32_t r;
    asm("cvt.rna.tf32.f32 %0, %1;" : "=r"(r) : "f"(x));
    return r;
}

__device__ __forceinline__ void mma_tf32(float* c, const uint32_t* a, const uint32_t* b) {
    asm volatile(
        "mma.sync.aligned.m16n8k8.row.col.f32.tf32.tf32.f32 "
        "{%0,%1,%2,%3}, {%4,%5,%6,%7}, {%8,%9}, {%0,%1,%2,%3};\n"
        : "+f"(c[0]), "+f"(c[1]), "+f"(c[2]), "+f"(c[3])
        : "r"(a[0]), "r"(a[1]), "r"(a[2]), "r"(a[3]), "r"(b[0]), "r"(b[1]));
}

// ------------------------- CSR build -------------------------
// launch #1: init degrees to 1 (self-loop) + histogram of dst (grid-stride)
__global__ void k_deg(const int* __restrict__ ei, int E, int N) {
    int i = blockIdx.x * blockDim.x + threadIdx.x;
    if (i < N) g_deg[i] = 1;
    __threadfence();
    // second phase handled by separate grid pass below via grid-stride over E,
    // but we must not read g_deg before all writes: instead split by index space.
    // NOTE: histogram is done in a dedicated region: threads [0, E) offset by N-pad.
    // To stay single-kernel and race-free we use atomicAdd only after the owner
    // thread wrote its slot -- guaranteed because atomicAdd targets may belong to
    // other blocks. So instead: initialize via atomicExch pattern is unsafe.
    // => do histogram in the same kernel but on a SECOND grid-stride sweep is
    // still racy across blocks. Keep it simple: histogram moved to k_hist below.
}
__global__ void k_hist(const int* __restrict__ ei, int E) {
    int i = blockIdx.x * blockDim.x + threadIdx.x;
    if (i < E) atomicAdd(&g_deg[ei[E + i]], 1);
}
__global__ void k_scanblk(int N) {
    __shared__ int sh[256];
    int i = blockIdx.x * 256 + threadIdx.x;
    int v = (i < N) ? g_deg[i] : 0;
    sh[threadIdx.x] = v;
    __syncthreads();
    for (int off = 1; off < 256; off <<= 1) {
        int t = (threadIdx.x >= off) ? sh[threadIdx.x - off] : 0;
        __syncthreads();
        sh[threadIdx.x] += t;
        __syncthreads();
    }
    if (i < N) g_pre[i] = sh[threadIdx.x] - v;   // exclusive
    if (threadIdx.x == 255) g_bsum[blockIdx.x] = sh[255];
}
// launch #3: top-level scan + (piggyback) nothing else
__global__ void k_scantop(int NB) {
    __shared__ int sh[256];
    int v = (threadIdx.x < NB) ? g_bsum[threadIdx.x] : 0;
    sh[threadIdx.x] = v;
    __syncthreads();
    for (int off = 1; off < 256; off <<= 1) {
        int t = (threadIdx.x >= off) ? sh[threadIdx.x - off] : 0;
        __syncthreads();
        sh[threadIdx.x] += t;
        __syncthreads();
    }
    if (threadIdx.x < NB) g_bsum[threadIdx.x] = sh[threadIdx.x] - v;  // exclusive
}
__global__ void k_finalize(int N, int Etot) {
    int i = blockIdx.x * blockDim.x + threadIdx.x;
    if (i < N) {
        int rp = g_pre[i] + g_bsum[i >> 8];
        g_rowptr[i] = rp;
        g_cursor[i] = rp + 1;
        g_esrc[rp] = i;                   // self-loop occupies first slot
        if (i == 0) g_rowptr[N] = Etot;
    }
}
__global__ void k_scatter(const int* __restrict__ ei, int E) {
    int i = blockIdx.x * blockDim.x + threadIdx.x;
    if (i < E) {
        int d = ei[E + i];
        int slot = atomicAdd(&g_cursor[d], 1);
        g_esrc[slot] = ei[i];
    }
}

// --------------- 3xTF32 tensor-core GEMM: C = A[M,K] @ W[K,BN] + bias ---------------
// BM=128, BK=16, 256 threads = 8 warps (2 m-warps x 4 n-warps).
// SRC: 0 = Aarg, 1 = g_h1, 2 = g_h2.
// DSTSEL: 0 = Carg (ldc=BN), 1 = y-select (xl1,xr1) ldc=128, 2 = y-select (xl2,xr2) ldc=64.
template <int K, int BN, int ACT, int SRC, int DSTSEL>
__global__ __launch_bounds__(256) void k_gemm_tc(const float* __restrict__ Aarg,
                                                 const float* __restrict__ W0,
                                                 const float* __restrict__ W1,
                                                 const float* __restrict__ b0,
                                                 const float* __restrict__ b1,
                                                 float* __restrict__ Carg, int M) {
    const int NF = BN / 32;
    const int ASTR = 20;
    const int BSTR = BN + 8;

    const float* A = (SRC == 0) ? Aarg : (SRC == 1 ? g_h1 : g_h2);
    const float* W    = (blockIdx.y == 0) ? W0 : W1;
    const float* bias = (blockIdx.y == 0) ? b0 : b1;
    float* C;
    int ldc;
    if (DSTSEL == 0)      { C = Carg; ldc = BN; }
    else if (DSTSEL == 1) { C = (blockIdx.y == 0) ? g_xl1 : g_xr1; ldc = 128; }
    else                  { C = (blockIdx.y == 0) ? g_xl2 : g_xr2; ldc = 64; }

    __shared__ float Ah[128][ASTR];
    __shared__ float Al[128][ASTR];
    __shared__ float Bh[16][BSTR];
    __shared__ float Bl[16][BSTR];

    int tid  = threadIdx.x;
    int lane = tid & 31;
    int ww   = tid >> 5;
    int bm   = blockIdx.x * 128;
    int wm0  = (ww & 1) * 64;
    int wn0  = (ww >> 1) * (BN / 4);
    int tg   = lane & 3;
    int gid  = lane >> 2;

    float acc[4][NF][4] = {};

#pragma unroll 1
    for (int k0 = 0; k0 < K; k0 += 16) {
        {
            int row = tid >> 1;
            int arow = bm + row; if (arow >= M) arow = M - 1;
#pragma unroll
            for (int r = 0; r < 2; r++) {
                int cq = (tid & 1) * 2 + r;
                float4 v = *(const float4*)(A + (size_t)arow * K + k0 + cq * 4);
                float4 h, l;
                h.x = __uint_as_float(f2tf32(v.x)); l.x = __uint_as_float(f2tf32(v.x - h.x));
                h.y = __uint_as_float(f2tf32(v.y)); l.y = __uint_as_float(f2tf32(v.y - h.y));
                h.z = __uint_as_float(f2tf32(v.z)); l.z = __uint_as_float(f2tf32(v.z - h.z));
                h.w = __uint_as_float(f2tf32(v.w)); l.w = __uint_as_float(f2tf32(v.w - h.w));
                *(float4*)&Ah[row][cq * 4] = h;
                *(float4*)&Al[row][cq * 4] = l;
            }
        }
        {
            const int NF4 = BN / 4;
#pragma unroll
            for (int q = tid; q < 16 * NF4; q += 256) {
                int row = q / NF4, cf = q % NF4;
                float4 v = *(const float4*)(W + (size_t)(k0 + row) * BN + cf * 4);
                float4 h, l;
                h.x = __uint_as_float(f2tf32(v.x)); l.x = __uint_as_float(f2tf32(v.x - h.x));
                h.y = __uint_as_float(f2tf32(v.y)); l.y = __uint_as_float(f2tf32(v.y - h.y));
                h.z = __uint_as_float(f2tf32(v.z)); l.z = __uint_as_float(f2tf32(v.z - h.z));
                h.w = __uint_as_float(f2tf32(v.w)); l.w = __uint_as_float(f2tf32(v.w - h.w));
                *(float4*)&Bh[row][cf * 4] = h;
                *(float4*)&Bl[row][cf * 4] = l;
            }
        }
        __syncthreads();

#pragma unroll
        for (int ks = 0; ks < 2; ks++) {
            int kb = ks * 8;
            uint32_t ah[4][4], al[4][4];
#pragma unroll
            for (int im = 0; im < 4; im++) {
                int mr = wm0 + im * 16 + gid;
                ah[im][0] = __float_as_uint(Ah[mr][kb + tg]);
                ah[im][1] = __float_as_uint(Ah[mr + 8][kb + tg]);
                ah[im][2] = __float_as_uint(Ah[mr][kb + tg + 4]);
                ah[im][3] = __float_as_uint(Ah[mr + 8][kb + tg + 4]);
                al[im][0] = __float_as_uint(Al[mr][kb + tg]);
                al[im][1] = __float_as_uint(Al[mr + 8][kb + tg]);
                al[im][2] = __float_as_uint(Al[mr][kb + tg + 4]);
                al[im][3] = __float_as_uint(Al[mr + 8][kb + tg + 4]);
            }
            uint32_t bh[NF][2], bl[NF][2];
#pragma unroll
            for (int in = 0; in < NF; in++) {
                int nc = wn0 + in * 8 + gid;
                bh[in][0] = __float_as_uint(Bh[kb + tg][nc]);
                bh[in][1] = __float_as_uint(Bh[kb + tg + 4][nc]);
                bl[in][0] = __float_as_uint(Bl[kb + tg][nc]);
                bl[in][1] = __float_as_uint(Bl[kb + tg + 4][nc]);
            }
#pragma unroll
            for (int im = 0; im < 4; im++)
#pragma unroll
                for (int in = 0; in < NF; in++) {
                    mma_tf32(acc[im][in], ah[im], bh[in]);
                    mma_tf32(acc[im][in], al[im], bh[in]);
                    mma_tf32(acc[im][in], ah[im], bl[in]);
                }
        }
        __syncthreads();
    }

#pragma unroll
    for (int im = 0; im < 4; im++) {
        int r0 = bm + wm0 + im * 16 + gid;
#pragma unroll
        for (int in = 0; in < NF; in++) {
            int cc = wn0 + in * 8 + 2 * tg;
            float bx = bias[cc], by = bias[cc + 1];
            if (r0 < M) {
                float2 v = make_float2(acc[im][in][0] + bx, acc[im][in][1] + by);
                if (ACT) { v.x = elu1(v.x); v.y = elu1(v.y); }
                *(float2*)(C + (size_t)r0 * ldc + cc) = v;
            }
            if (r0 + 8 < M) {
                float2 v = make_float2(acc[im][in][2] + bx, acc[im][in][3] + by);
                if (ACT) { v.x = elu1(v.x); v.y = elu1(v.y); }
                *(float2*)(C + (size_t)(r0 + 8) * ldc + cc) = v;
            }
        }
    }
}

// --------- layer 1 edge+softmax+aggregate+norm+bias+ELU, CSR, warp per node ---------
// H=8, C=16; lane covers 4 channels of head (lane>>2). Unshifted softmax (shift-
// invariant; logits « 88, self-loop keeps den>0). 2-deep src-row prefetch.
__global__ void k_edge1_csr(const float* __restrict__ att,
                            const float* __restrict__ bias, int N) {
    int gt = blockIdx.x * blockDim.x + threadIdx.x;
    int lane = gt & 31, w = gt >> 5;
    if (w >= N) return;

    float4 attr = *(const float4*)(att + lane * 4);
    float4 b = *(const float4*)(g_xr1 + (size_t)w * 128 + lane * 4);

    int beg = g_rowptr[w];
    int n = g_rowptr[w + 1] - beg;
    float4 acc = make_float4(0.f, 0.f, 0.f, 0.f);
    float den = 0.f;

    float4 A0 = *(const float4*)(g_xl1 + (size_t)g_esrc[beg] * 128 + lane * 4);
    float4 A1 = A0;
    if (n > 1) A1 = *(const float4*)(g_xl1 + (size_t)g_esrc[beg + 1] * 128 + lane * 4);

    for (int p = 0; p < n; p++) {
        float4 ac = A0;
        A0 = A1;
        if (p + 2 < n)
            A1 = *(const float4*)(g_xl1 + (size_t)g_esrc[beg + p + 2] * 128 + lane * 4);

        float z0 = ac.x + b.x; z0 = z0 > 0.f ? z0 : 0.2f * z0;
        float z1 = ac.y + b.y; z1 = z1 > 0.f ? z1 : 0.2f * z1;
        float z2 = ac.z + b.z; z2 = z2 > 0.f ? z2 : 0.2f * z2;
        float z3 = ac.w + b.w; z3 = z3 > 0.f ? z3 : 0.2f * z3;
        float part = attr.x * z0 + attr.y * z1 + attr.z * z2 + attr.w * z3;
        part += __shfl_xor_sync(0xffffffffu, part, 1);
        part += __shfl_xor_sync(0xffffffffu, part, 2);
        float ex = __expf(part);
        den += ex;
        acc.x += ac.x * ex; acc.y += ac.y * ex;
        acc.z += ac.z * ex; acc.w += ac.w * ex;
    }

    float inv = 1.f / den;
    int c = lane * 4;
    float4 o;
    o.x = elu1(acc.x * inv + bias[c + 0]);
    o.y = elu1(acc.y * inv + bias[c + 1]);
    o.z = elu1(acc.z * inv + bias[c + 2]);
    o.w = elu1(acc.w * inv + bias[c + 3]);
    *(float4*)(g_h1 + (size_t)w * 128 + c) = o;
}

// --------- layer 2 edge pass, CSR, warp per node; H=1, C=64; lane = 2 channels ---------
__global__ void k_edge2_csr(const float* __restrict__ att,
                            const float* __restrict__ bias, int N) {
    int gt = blockIdx.x * blockDim.x + threadIdx.x;
    int lane = gt & 31, w = gt >> 5;
    if (w >= N) return;

    float2 attr = *(const float2*)(att + lane * 2);
    float2 b = *(const float2*)(g_xr2 + (size_t)w * 64 + lane * 2);

    int beg = g_rowptr[w];
    int n = g_rowptr[w + 1] - beg;
    float2 acc = make_float2(0.f, 0.f);
    float den = 0.f;

    float2 A0 = *(const float2*)(g_xl2 + (size_t)g_esrc[beg] * 64 + lane * 2);
    float2 A1 = A0;
    if (n > 1) A1 = *(const float2*)(g_xl2 + (size_t)g_esrc[beg + 1] * 64 + lane * 2);

    for (int p = 0; p < n; p++) {
        float2 ac = A0;
        A0 = A1;
        if (p + 2 < n)
            A1 = *(const float2*)(g_xl2 + (size_t)g_esrc[beg + p + 2] * 64 + lane * 2);

        float z0 = ac.x + b.x; z0 = z0 > 0.f ? z0 : 0.2f * z0;
        float z1 = ac.y + b.y; z1 = z1 > 0.f ? z1 : 0.2f * z1;
        float part = attr.x * z0 + attr.y * z1;
        part += __shfl_xor_sync(0xffffffffu, part, 1);
        part += __shfl_xor_sync(0xffffffffu, part, 2);
        part += __shfl_xor_sync(0xffffffffu, part, 4);
        part += __shfl_xor_sync(0xffffffffu, part, 8);
        part += __shfl_xor_sync(0xffffffffu, part, 16);
        float ex = __expf(part);
        den += ex;
        acc.x += ac.x * ex; acc.y += ac.y * ex;
    }

    float inv = 1.f / den;
    int c = lane * 2;
    float2 o;
    o.x = elu1(acc.x * inv + bias[c + 0]);
    o.y = elu1(acc.y * inv + bias[c + 1]);
    *(float2*)(g_h2 + (size_t)w * 64 + c) = o;
}

// ------------------------- launch -------------------------
static inline int cdiv(int a, int b) { return (a + b - 1) / b; }

extern "C" void kernel_launch(void* const* d_in, const int* in_sizes, int n_in,
                              void* d_out, int out_size) {
    const float* x     = (const float*)d_in[0];
    const int*   ei    = (const int*)d_in[1];
    const float* Wl1   = (const float*)d_in[2];
    const float* bl1   = (const float*)d_in[3];
    const float* Wr1   = (const float*)d_in[4];
    const float* br1   = (const float*)d_in[5];
    const float* att1  = (const float*)d_in[6];
    const float* bias1 = (const float*)d_in[7];
    const float* Wl2   = (const float*)d_in[8];
    const float* bl2   = (const float*)d_in[9];
    const float* Wr2   = (const float*)d_in[10];
    const float* br2   = (const float*)d_in[11];
    const float* att2  = (const float*)d_in[12];
    const float* bias2 = (const float*)d_in[13];
    const float* Wlin  = (const float*)d_in[14];
    const float* blin  = (const float*)d_in[15];

    int N = in_sizes[0] / 128;
    int E = in_sizes[1] / 2;
    int Etot = E + N;
    int NB = cdiv(N, 256);

    // ---- CSR build: exactly 5 launches so dual-GEMM-1 is launch #6 (ncu -s 5) ----
    k_deg<<<NB, 256>>>(ei, E, N);                    // #1 degrees=1
    k_hist<<<cdiv(E, 256), 256>>>(ei, E);            // #2 histogram
    k_scanblk<<<NB, 256>>>(N);                       // #3
    k_scantop<<<1, 256>>>(NB);                       // #4
    k_finalize<<<NB, 256>>>(N, Etot);                // #5

    // ---- layer 1 dual GEMM (launch #6 — profiled) ----
    dim3 g1(cdiv(N, 128), 2);
    k_gemm_tc<128, 128, 0, 0, 1><<<g1, 256>>>(x, Wl1, Wr1, bl1, br1, nullptr, N);

    k_scatter<<<cdiv(E, 256), 256>>>(ei, E);         // #7 (edge list fill)

    k_edge1_csr<<<cdiv(N * 32, 256), 256>>>(att1, bias1, N);

    // ---- layer 2: GATv2 (H=1, C=64) ----
    dim3 g2(cdiv(N, 128), 2);
    k_gemm_tc<128, 64, 0, 1, 2><<<g2, 256>>>(nullptr, Wl2, Wr2, bl2, br2, nullptr, N);
    k_edge2_csr<<<cdiv(N * 32, 256), 256>>>(att2, bias2, N);

    // ---- final linear + ELU -> d_out [N,128] ----
    dim3 g3(cdiv(N, 128), 1);
    k_gemm_tc<64, 128, 1, 2, 0><<<g3, 256>>>(nullptr, Wlin, Wlin, blin, blin, (float*)d_out, N);
}

// round 8
// speedup vs baseline: 1.0494x; 1.0494x over previous
#include <cuda_runtime.h>
#include <cuda_bf16.h>
#include <cstdint>

#define NMAX    50048
#define EMAX    800000
#define ETOTMAX (NMAX + EMAX)
#define NBLKMAX 256

// ------------------------- scratch (device globals) -------------------------
__device__ __align__(16) float g_xl1[NMAX * 128];
__device__ __align__(16) float g_xr1[NMAX * 128];
__device__ __align__(16) float g_h1[NMAX * 128];
__device__ __align__(16) float g_xl2[NMAX * 64];
__device__ __align__(16) float g_xr2[NMAX * 64];
__device__ __align__(16) float g_h2[NMAX * 64];
__device__ __align__(16) int   g_deg[NMAX];
__device__ __align__(16) int   g_pre[NMAX];
__device__ __align__(16) int   g_bsum[NBLKMAX];
__device__ __align__(16) int   g_rowptr[NMAX + 1];
__device__ __align__(16) int   g_cursor[NMAX];
__device__ __align__(16) int   g_esrc[ETOTMAX];

// ------------------------- helpers -------------------------
__device__ __forceinline__ float elu1(float v) { return v > 0.f ? v : expm1f(v); }

__device__ __forceinline__ void mma_bf16(float* c, const uint32_t* a, const uint32_t* b) {
    asm volatile(
        "mma.sync.aligned.m16n8k16.row.col.f32.bf16.bf16.f32 "
        "{%0,%1,%2,%3}, {%4,%5,%6,%7}, {%8,%9}, {%0,%1,%2,%3};\n"
        : "+f"(c[0]), "+f"(c[1]), "+f"(c[2]), "+f"(c[3])
        : "r"(a[0]), "r"(a[1]), "r"(a[2]), "r"(a[3]), "r"(b[0]), "r"(b[1]));
}

// ------------------------- CSR build -------------------------
__global__ void k_initdeg(int N) {
    int i = blockIdx.x * blockDim.x + threadIdx.x;
    if (i < N) g_deg[i] = 1;              // self-loop
}
__global__ void k_hist(const int* __restrict__ ei, int E) {
    int i = blockIdx.x * blockDim.x + threadIdx.x;
    if (i < E) atomicAdd(&g_deg[ei[E + i]], 1);
}
__global__ void k_scanblk(int N) {
    __shared__ int sh[256];
    int i = blockIdx.x * 256 + threadIdx.x;
    int v = (i < N) ? g_deg[i] : 0;
    sh[threadIdx.x] = v;
    __syncthreads();
    for (int off = 1; off < 256; off <<= 1) {
        int t = (threadIdx.x >= off) ? sh[threadIdx.x - off] : 0;
        __syncthreads();
        sh[threadIdx.x] += t;
        __syncthreads();
    }
    if (i < N) g_pre[i] = sh[threadIdx.x] - v;   // exclusive
    if (threadIdx.x == 255) g_bsum[blockIdx.x] = sh[255];
}
__global__ void k_scantop(int NB) {
    __shared__ int sh[256];
    int v = (threadIdx.x < NB) ? g_bsum[threadIdx.x] : 0;
    sh[threadIdx.x] = v;
    __syncthreads();
    for (int off = 1; off < 256; off <<= 1) {
        int t = (threadIdx.x >= off) ? sh[threadIdx.x - off] : 0;
        __syncthreads();
        sh[threadIdx.x] += t;
        __syncthreads();
    }
    if (threadIdx.x < NB) g_bsum[threadIdx.x] = sh[threadIdx.x] - v;  // exclusive
}
__global__ void k_finalize(int N, int Etot) {
    int i = blockIdx.x * blockDim.x + threadIdx.x;
    if (i < N) {
        int rp = g_pre[i] + g_bsum[i >> 8];
        g_rowptr[i] = rp;
        g_cursor[i] = rp + 1;
        g_esrc[rp] = i;                   // self-loop occupies first slot
        if (i == 0) g_rowptr[N] = Etot;
    }
}
__global__ void k_scatter(const int* __restrict__ ei, int E) {
    int i = blockIdx.x * blockDim.x + threadIdx.x;
    if (i < E) {
        int d = ei[E + i];
        int slot = atomicAdd(&g_cursor[d], 1);
        g_esrc[slot] = ei[i];
    }
}

// --------------- bf16x3-split tensor GEMM: C = A[M,K] @ W[K,BN] + bias ---------------
// BM=128, BK=32 (2 k16 steps), 256 threads = 8 warps (2m x 4n).
// A = Ah + Al (bf16 hi/lo); C ≈ Ah·Bh + Ah·Bl + Al·Bh  (ll term ~2^-18, dropped).
// SRC: 0 = Aarg, 1 = g_h1, 2 = g_h2.
// DSTSEL: 0 = Carg (ldc=BN), 1 = y-sel (xl1,xr1) ldc=128, 2 = y-sel (xl2,xr2) ldc=64.
template <int K, int BN, int ACT, int SRC, int DSTSEL>
__global__ __launch_bounds__(256) void k_gemm_bf(const float* __restrict__ Aarg,
                                                 const float* __restrict__ W0,
                                                 const float* __restrict__ W1,
                                                 const float* __restrict__ b0,
                                                 const float* __restrict__ b1,
                                                 float* __restrict__ Carg, int M) {
    const int NF = BN / 32;                  // n-fragments per warp (4 or 2)
    const int SSTR = 40;                     // bf16 row stride (80 B) -> conflict-free frags

    const float* A = (SRC == 0) ? Aarg : (SRC == 1 ? g_h1 : g_h2);
    const float* W    = (blockIdx.y == 0) ? W0 : W1;
    const float* bias = (blockIdx.y == 0) ? b0 : b1;
    float* C;
    int ldc;
    if (DSTSEL == 0)      { C = Carg; ldc = BN; }
    else if (DSTSEL == 1) { C = (blockIdx.y == 0) ? g_xl1 : g_xr1; ldc = 128; }
    else                  { C = (blockIdx.y == 0) ? g_xl2 : g_xr2; ldc = 64; }

    __shared__ __nv_bfloat16 Ah[128][SSTR];
    __shared__ __nv_bfloat16 Al[128][SSTR];
    __shared__ __nv_bfloat16 Bh[BN][SSTR];   // stored [col][k]
    __shared__ __nv_bfloat16 Bl[BN][SSTR];

    int tid  = threadIdx.x;
    int lane = tid & 31;
    int ww   = tid >> 5;
    int bm   = blockIdx.x * 128;
    int wm0  = (ww & 1) * 64;
    int wn0  = (ww >> 1) * (BN / 4);
    int tg   = lane & 3;                     // thread-in-group
    int gid  = lane >> 2;                    // group id (0..7)

    float acc[4][NF][4] = {};

#pragma unroll 1
    for (int k0 = 0; k0 < K; k0 += 32) {
        // ---- A tile fill: 128 rows x 32 k; thread = half-row (16 elems) ----
        {
            int row = tid >> 1;
            int ch  = (tid & 1) * 16;
            int arow = bm + row; if (arow >= M) arow = M - 1;
            const float* src = A + (size_t)arow * K + k0 + ch;
            union { __nv_bfloat16 h[16]; uint4 u[2]; } ph, pl;
#pragma unroll
            for (int q = 0; q < 4; q++) {
                float4 v = *(const float4*)(src + q * 4);
                float hx = __bfloat162float(__float2bfloat16_rn(v.x));
                float hy = __bfloat162float(__float2bfloat16_rn(v.y));
                float hz = __bfloat162float(__float2bfloat16_rn(v.z));
                float hw = __bfloat162float(__float2bfloat16_rn(v.w));
                ph.h[q * 4 + 0] = __float2bfloat16_rn(hx);
                ph.h[q * 4 + 1] = __float2bfloat16_rn(hy);
                ph.h[q * 4 + 2] = __float2bfloat16_rn(hz);
                ph.h[q * 4 + 3] = __float2bfloat16_rn(hw);
                pl.h[q * 4 + 0] = __float2bfloat16_rn(v.x - hx);
                pl.h[q * 4 + 1] = __float2bfloat16_rn(v.y - hy);
                pl.h[q * 4 + 2] = __float2bfloat16_rn(v.z - hz);
                pl.h[q * 4 + 3] = __float2bfloat16_rn(v.w - hw);
            }
            *(uint4*)&Ah[row][ch]     = ph.u[0];
            *(uint4*)&Ah[row][ch + 8] = ph.u[1];
            *(uint4*)&Al[row][ch]     = pl.u[0];
            *(uint4*)&Al[row][ch + 8] = pl.u[1];
        }
        // ---- B tile fill (transposed to [col][k]): 32 k-rows x BN cols ----
        {
            const int NF4 = BN / 4;
#pragma unroll
            for (int q = tid; q < 32 * NF4; q += 256) {
                int kr = q / NF4, cf = q % NF4;
                float4 v = *(const float4*)(W + (size_t)(k0 + kr) * BN + cf * 4);
                int c0 = cf * 4;
                float hx = __bfloat162float(__float2bfloat16_rn(v.x));
                float hy = __bfloat162float(__float2bfloat16_rn(v.y));
                float hz = __bfloat162float(__float2bfloat16_rn(v.z));
                float hw = __bfloat162float(__float2bfloat16_rn(v.w));
                Bh[c0 + 0][kr] = __float2bfloat16_rn(hx);
                Bh[c0 + 1][kr] = __float2bfloat16_rn(hy);
                Bh[c0 + 2][kr] = __float2bfloat16_rn(hz);
                Bh[c0 + 3][kr] = __float2bfloat16_rn(hw);
                Bl[c0 + 0][kr] = __float2bfloat16_rn(v.x - hx);
                Bl[c0 + 1][kr] = __float2bfloat16_rn(v.y - hy);
                Bl[c0 + 2][kr] = __float2bfloat16_rn(v.z - hz);
                Bl[c0 + 3][kr] = __float2bfloat16_rn(v.w - hw);
            }
        }
        __syncthreads();

#pragma unroll
        for (int s = 0; s < 2; s++) {
            int kb = s * 16;
            uint32_t ah[4][4], al[4][4];
#pragma unroll
            for (int im = 0; im < 4; im++) {
                int mr = wm0 + im * 16 + gid;
                ah[im][0] = *(const uint32_t*)&Ah[mr][kb + 2 * tg];
                ah[im][1] = *(const uint32_t*)&Ah[mr + 8][kb + 2 * tg];
                ah[im][2] = *(const uint32_t*)&Ah[mr][kb + 2 * tg + 8];
                ah[im][3] = *(const uint32_t*)&Ah[mr + 8][kb + 2 * tg + 8];
                al[im][0] = *(const uint32_t*)&Al[mr][kb + 2 * tg];
                al[im][1] = *(const uint32_t*)&Al[mr + 8][kb + 2 * tg];
                al[im][2] = *(const uint32_t*)&Al[mr][kb + 2 * tg + 8];
                al[im][3] = *(const uint32_t*)&Al[mr + 8][kb + 2 * tg + 8];
            }
            uint32_t bh[NF][2], bl[NF][2];
#pragma unroll
            for (int in = 0; in < NF; in++) {
                int nc = wn0 + in * 8 + gid;
                bh[in][0] = *(const uint32_t*)&Bh[nc][kb + 2 * tg];
                bh[in][1] = *(const uint32_t*)&Bh[nc][kb + 2 * tg + 8];
                bl[in][0] = *(const uint32_t*)&Bl[nc][kb + 2 * tg];
                bl[in][1] = *(const uint32_t*)&Bl[nc][kb + 2 * tg + 8];
            }
#pragma unroll
            for (int im = 0; im < 4; im++)
#pragma unroll
                for (int in = 0; in < NF; in++) {
                    mma_bf16(acc[im][in], ah[im], bh[in]);
                    mma_bf16(acc[im][in], ah[im], bl[in]);
                    mma_bf16(acc[im][in], al[im], bh[in]);
                }
        }
        __syncthreads();
    }

    // epilogue: bias (+ELU); c0,c1 = (gid,2tg..), c2,c3 = (gid+8,2tg..)
#pragma unroll
    for (int im = 0; im < 4; im++) {
        int r0 = bm + wm0 + im * 16 + gid;
#pragma unroll
        for (int in = 0; in < NF; in++) {
            int cc = wn0 + in * 8 + 2 * tg;
            float bx = bias[cc], by = bias[cc + 1];
            if (r0 < M) {
                float2 v = make_float2(acc[im][in][0] + bx, acc[im][in][1] + by);
                if (ACT) { v.x = elu1(v.x); v.y = elu1(v.y); }
                *(float2*)(C + (size_t)r0 * ldc + cc) = v;
            }
            if (r0 + 8 < M) {
                float2 v = make_float2(acc[im][in][2] + bx, acc[im][in][3] + by);
                if (ACT) { v.x = elu1(v.x); v.y = elu1(v.y); }
                *(float2*)(C + (size_t)(r0 + 8) * ldc + cc) = v;
            }
        }
    }
}

// --------- layer 1 edge+softmax+aggregate+norm+bias+ELU, CSR, warp per node ---------
__global__ void k_edge1_csr(const float* __restrict__ att,
                            const float* __restrict__ bias, int N) {
    int gt = blockIdx.x * blockDim.x + threadIdx.x;
    int lane = gt & 31, w = gt >> 5;
    if (w >= N) return;

    float4 attr = *(const float4*)(att + lane * 4);
    float4 b = *(const float4*)(g_xr1 + (size_t)w * 128 + lane * 4);

    int beg = g_rowptr[w], end = g_rowptr[w + 1];
    float4 acc = make_float4(0.f, 0.f, 0.f, 0.f);
    float den = 0.f;

    int s = g_esrc[beg];
    float4 a = *(const float4*)(g_xl1 + (size_t)s * 128 + lane * 4);
    for (int p = beg; p < end; p++) {
        float4 ac = a;
        if (p + 1 < end) {
            s = g_esrc[p + 1];
            a = *(const float4*)(g_xl1 + (size_t)s * 128 + lane * 4);
        }
        float z0 = ac.x + b.x; z0 = z0 > 0.f ? z0 : 0.2f * z0;
        float z1 = ac.y + b.y; z1 = z1 > 0.f ? z1 : 0.2f * z1;
        float z2 = ac.z + b.z; z2 = z2 > 0.f ? z2 : 0.2f * z2;
        float z3 = ac.w + b.w; z3 = z3 > 0.f ? z3 : 0.2f * z3;
        float part = attr.x * z0 + attr.y * z1 + attr.z * z2 + attr.w * z3;
        part += __shfl_xor_sync(0xffffffffu, part, 1);
        part += __shfl_xor_sync(0xffffffffu, part, 2);
        float ex = __expf(part);
        den += ex;
        acc.x += ac.x * ex; acc.y += ac.y * ex;
        acc.z += ac.z * ex; acc.w += ac.w * ex;
    }

    float inv = 1.f / den;
    int c = lane * 4;
    float4 o;
    o.x = elu1(acc.x * inv + bias[c + 0]);
    o.y = elu1(acc.y * inv + bias[c + 1]);
    o.z = elu1(acc.z * inv + bias[c + 2]);
    o.w = elu1(acc.w * inv + bias[c + 3]);
    *(float4*)(g_h1 + (size_t)w * 128 + c) = o;
}

// --------- layer 2 edge pass, CSR, warp per node; H=1, C=64 ---------
__global__ void k_edge2_csr(const float* __restrict__ att,
                            const float* __restrict__ bias, int N) {
    int gt = blockIdx.x * blockDim.x + threadIdx.x;
    int lane = gt & 31, w = gt >> 5;
    if (w >= N) return;

    float2 attr = *(const float2*)(att + lane * 2);
    float2 b = *(const float2*)(g_xr2 + (size_t)w * 64 + lane * 2);

    int beg = g_rowptr[w], end = g_rowptr[w + 1];
    float2 acc = make_float2(0.f, 0.f);
    float den = 0.f;

    int s = g_esrc[beg];
    float2 a = *(const float2*)(g_xl2 + (size_t)s * 64 + lane * 2);
    for (int p = beg; p < end; p++) {
        float2 ac = a;
        if (p + 1 < end) {
            s = g_esrc[p + 1];
            a = *(const float2*)(g_xl2 + (size_t)s * 64 + lane * 2);
        }
        float z0 = ac.x + b.x; z0 = z0 > 0.f ? z0 : 0.2f * z0;
        float z1 = ac.y + b.y; z1 = z1 > 0.f ? z1 : 0.2f * z1;
        float part = attr.x * z0 + attr.y * z1;
        part += __shfl_xor_sync(0xffffffffu, part, 1);
        part += __shfl_xor_sync(0xffffffffu, part, 2);
        part += __shfl_xor_sync(0xffffffffu, part, 4);
        part += __shfl_xor_sync(0xffffffffu, part, 8);
        part += __shfl_xor_sync(0xffffffffu, part, 16);
        float ex = __expf(part);
        den += ex;
        acc.x += ac.x * ex; acc.y += ac.y * ex;
    }

    float inv = 1.f / den;
    int c = lane * 2;
    float2 o;
    o.x = elu1(acc.x * inv + bias[c + 0]);
    o.y = elu1(acc.y * inv + bias[c + 1]);
    *(float2*)(g_h2 + (size_t)w * 64 + c) = o;
}

// ------------------------- launch -------------------------
static inline int cdiv(int a, int b) { return (a + b - 1) / b; }

extern "C" void kernel_launch(void* const* d_in, const int* in_sizes, int n_in,
                              void* d_out, int out_size) {
    const float* x     = (const float*)d_in[0];
    const int*   ei    = (const int*)d_in[1];
    const float* Wl1   = (const float*)d_in[2];
    const float* bl1   = (const float*)d_in[3];
    const float* Wr1   = (const float*)d_in[4];
    const float* br1   = (const float*)d_in[5];
    const float* att1  = (const float*)d_in[6];
    const float* bias1 = (const float*)d_in[7];
    const float* Wl2   = (const float*)d_in[8];
    const float* bl2   = (const float*)d_in[9];
    const float* Wr2   = (const float*)d_in[10];
    const float* br2   = (const float*)d_in[11];
    const float* att2  = (const float*)d_in[12];
    const float* bias2 = (const float*)d_in[13];
    const float* Wlin  = (const float*)d_in[14];
    const float* blin  = (const float*)d_in[15];

    int N = in_sizes[0] / 128;
    int E = in_sizes[1] / 2;
    int Etot = E + N;
    int NB = cdiv(N, 256);

    // ---- CSR build (dst-sorted, self-loop first per segment) ----
    k_initdeg<<<NB, 256>>>(N);
    k_hist<<<cdiv(E, 256), 256>>>(ei, E);
    k_scanblk<<<NB, 256>>>(N);
    k_scantop<<<1, 256>>>(NB);
    k_finalize<<<NB, 256>>>(N, Etot);
    k_scatter<<<cdiv(E, 256), 256>>>(ei, E);

    // ---- layer 1: GATv2 (H=8, C=16, concat) ----
    dim3 g1(cdiv(N, 128), 2);
    k_gemm_bf<128, 128, 0, 0, 1><<<g1, 256>>>(x, Wl1, Wr1, bl1, br1, nullptr, N);
    k_edge1_csr<<<cdiv(N * 32, 256), 256>>>(att1, bias1, N);

    // ---- layer 2: GATv2 (H=1, C=64) ----
    dim3 g2(cdiv(N, 128), 2);
    k_gemm_bf<128, 64, 0, 1, 2><<<g2, 256>>>(nullptr, Wl2, Wr2, bl2, br2, nullptr, N);
    k_edge2_csr<<<cdiv(N * 32, 256), 256>>>(att2, bias2, N);

    // ---- final linear + ELU -> d_out [N,128] ----
    dim3 g3(cdiv(N, 128), 1);
    k_gemm_bf<64, 128, 1, 2, 0><<<g3, 256>>>(nullptr, Wlin, Wlin, blin, blin, (float*)d_out, N);
}

// round 10
// speedup vs baseline: 1.2396x; 1.1813x over previous
#include <cuda_runtime.h>
#include <cuda_bf16.h>
#include <cstdint>

#define NMAX    50048
#define EMAX    800000
#define ETOTMAX (NMAX + EMAX)
#define NBLKMAX 256

// ------------------------- scratch (device globals) -------------------------
__device__ __align__(16) float g_xl1[NMAX * 128];
__device__ __align__(16) float g_xr1[NMAX * 128];
__device__ __align__(16) float g_xl2[NMAX * 64];
__device__ __align__(16) float g_xr2[NMAX * 64];
// bf16 hi/lo GEMM inputs
__device__ __align__(16) __nv_bfloat16 g_xh [NMAX * 128];
__device__ __align__(16) __nv_bfloat16 g_xlo[NMAX * 128];
__device__ __align__(16) __nv_bfloat16 g_h1h[NMAX * 128];
__device__ __align__(16) __nv_bfloat16 g_h1l[NMAX * 128];
__device__ __align__(16) __nv_bfloat16 g_h2h[NMAX * 64];
__device__ __align__(16) __nv_bfloat16 g_h2l[NMAX * 64];
// weights, transposed to [col][k], bf16 hi/lo
__device__ __align__(16) __nv_bfloat16 g_w1h[2 * 128 * 128];
__device__ __align__(16) __nv_bfloat16 g_w1l[2 * 128 * 128];
__device__ __align__(16) __nv_bfloat16 g_w2h[2 * 64 * 128];
__device__ __align__(16) __nv_bfloat16 g_w2l[2 * 64 * 128];
__device__ __align__(16) __nv_bfloat16 g_w3h[128 * 64];
__device__ __align__(16) __nv_bfloat16 g_w3l[128 * 64];
// CSR
__device__ __align__(16) int g_deg[NMAX];
__device__ __align__(16) int g_pre[NMAX];
__device__ __align__(16) int g_bsum[NBLKMAX];
__device__ __align__(16) int g_rowptr[NMAX + 1];
__device__ __align__(16) int g_cursor[NMAX];
__device__ __align__(16) int g_esrc[ETOTMAX];

// ------------------------- helpers -------------------------
__device__ __forceinline__ float elu1(float v) { return v > 0.f ? v : expm1f(v); }

__device__ __forceinline__ void split_bf(float v, __nv_bfloat16& h, __nv_bfloat16& l) {
    h = __float2bfloat16_rn(v);
    l = __float2bfloat16_rn(v - __bfloat162float(h));
}

__device__ __forceinline__ void mma_bf16(float* c, const uint32_t* a, const uint32_t* b) {
    asm volatile(
        "mma.sync.aligned.m16n8k16.row.col.f32.bf16.bf16.f32 "
        "{%0,%1,%2,%3}, {%4,%5,%6,%7}, {%8,%9}, {%0,%1,%2,%3};\n"
        : "+f"(c[0]), "+f"(c[1]), "+f"(c[2]), "+f"(c[3])
        : "r"(a[0]), "r"(a[1]), "r"(a[2]), "r"(a[3]), "r"(b[0]), "r"(b[1]));
}

// ------------------------- conversions -------------------------
__global__ void k_cvtA(const float* __restrict__ x, int n) {
    int i = (blockIdx.x * blockDim.x + threadIdx.x) * 4;
    if (i < n) {
        float4 v = *(const float4*)(x + i);
        __nv_bfloat16 h[4], l[4];
        split_bf(v.x, h[0], l[0]); split_bf(v.y, h[1], l[1]);
        split_bf(v.z, h[2], l[2]); split_bf(v.w, h[3], l[3]);
        *(uint2*)(g_xh  + i) = *(uint2*)h;
        *(uint2*)(g_xlo + i) = *(uint2*)l;
    }
}

// transpose + split all weights: L1 (2x 128x128), L2 (2x 128x64), lin (64x128)
__global__ void k_cvtW(const float* __restrict__ Wl1, const float* __restrict__ Wr1,
                       const float* __restrict__ Wl2, const float* __restrict__ Wr2,
                       const float* __restrict__ Wlin) {
    int i = blockIdx.x * blockDim.x + threadIdx.x;   // 57344 total
    if (i < 32768) {                                  // L1: m, col(128), k(128)
        int m = i >> 14, r = i & 16383, c = r >> 7, k = r & 127;
        const float* W = m ? Wr1 : Wl1;
        split_bf(W[k * 128 + c], g_w1h[i], g_w1l[i]); // i = m*16384 + c*128 + k
    } else if (i < 49152) {                           // L2: m, col(64), k(128)
        int j = i - 32768;
        int m = j >> 13, r = j & 8191, c = r >> 7, k = r & 127;
        const float* W = m ? Wr2 : Wl2;
        split_bf(W[k * 64 + c], g_w2h[j], g_w2l[j]);  // j = m*8192 + c*128 + k
    } else {                                          // lin: col(128), k(64)
        int j = i - 49152;
        int c = j >> 6, k = j & 63;
        split_bf(Wlin[k * 128 + c], g_w3h[j], g_w3l[j]);
    }
}

// ------------------------- CSR build -------------------------
__global__ void k_initdeg(int N) {
    int i = blockIdx.x * blockDim.x + threadIdx.x;
    if (i < N) g_deg[i] = 1;              // self-loop
}
__global__ void k_hist(const int* __restrict__ ei, int E) {
    int i = blockIdx.x * blockDim.x + threadIdx.x;
    if (i < E) atomicAdd(&g_deg[ei[E + i]], 1);
}
__global__ void k_scanblk(int N) {
    __shared__ int sh[256];
    int i = blockIdx.x * 256 + threadIdx.x;
    int v = (i < N) ? g_deg[i] : 0;
    sh[threadIdx.x] = v;
    __syncthreads();
    for (int off = 1; off < 256; off <<= 1) {
        int t = (threadIdx.x >= off) ? sh[threadIdx.x - off] : 0;
        __syncthreads();
        sh[threadIdx.x] += t;
        __syncthreads();
    }
    if (i < N) g_pre[i] = sh[threadIdx.x] - v;   // exclusive
    if (threadIdx.x == 255) g_bsum[blockIdx.x] = sh[255];
}
__global__ void k_scantop(int NB) {
    __shared__ int sh[256];
    int v = (threadIdx.x < NB) ? g_bsum[threadIdx.x] : 0;
    sh[threadIdx.x] = v;
    __syncthreads();
    for (int off = 1; off < 256; off <<= 1) {
        int t = (threadIdx.x >= off) ? sh[threadIdx.x - off] : 0;
        __syncthreads();
        sh[threadIdx.x] += t;
        __syncthreads();
    }
    if (threadIdx.x < NB) g_bsum[threadIdx.x] = sh[threadIdx.x] - v;  // exclusive
}
__global__ void k_finalize(int N, int Etot) {
    int i = blockIdx.x * blockDim.x + threadIdx.x;
    if (i < N) {
        int rp = g_pre[i] + g_bsum[i >> 8];
        g_rowptr[i] = rp;
        g_cursor[i] = rp + 1;
        g_esrc[rp] = i;                   // self-loop occupies first slot
        if (i == 0) g_rowptr[N] = Etot;
    }
}
__global__ void k_scatter(const int* __restrict__ ei, int E) {
    int i = blockIdx.x * blockDim.x + threadIdx.x;
    if (i < E) {
        int d = ei[E + i];
        int slot = atomicAdd(&g_cursor[d], 1);
        g_esrc[slot] = ei[i];
    }
}

// --------------- bf16x3-split tensor GEMM, precomputed bf16 inputs ---------------
// C[M,BN] = A[M,K] @ W[K,BN] + bias;  A,W given as bf16 hi/lo; fills are pure copies.
// BM=128, BK=32, 256 threads = 8 warps (2m x 4n).
// SRC: 0 = g_xh/g_xlo (K=128), 1 = g_h1h/g_h1l (K=128), 2 = g_h2h/g_h2l (K=64).
// WSEL: 1 = g_w1 (+y*16384), 2 = g_w2 (+y*8192), 3 = g_w3.
// DSTSEL: 0 = Carg (ldc=BN), 1 = y-sel (xl1,xr1) ldc=128, 2 = y-sel (xl2,xr2) ldc=64.
template <int K, int BN, int ACT, int SRC, int WSEL, int DSTSEL>
__global__ __launch_bounds__(256) void k_gemm_bf(const float* __restrict__ b0,
                                                 const float* __restrict__ b1,
                                                 float* __restrict__ Carg, int M) {
    const int NF = BN / 32;
    const int SSTR = 40;                     // bf16 row stride (80 B)

    const __nv_bfloat16* Agh = (SRC == 0) ? g_xh : (SRC == 1 ? g_h1h : g_h2h);
    const __nv_bfloat16* Agl = (SRC == 0) ? g_xlo : (SRC == 1 ? g_h1l : g_h2l);
    const __nv_bfloat16* Bgh = (WSEL == 1) ? g_w1h + blockIdx.y * 16384
                              : (WSEL == 2) ? g_w2h + blockIdx.y * 8192 : g_w3h;
    const __nv_bfloat16* Bgl = (WSEL == 1) ? g_w1l + blockIdx.y * 16384
                              : (WSEL == 2) ? g_w2l + blockIdx.y * 8192 : g_w3l;
    const float* bias = (blockIdx.y == 0) ? b0 : b1;
    float* C;
    int ldc;
    if (DSTSEL == 0)      { C = Carg; ldc = BN; }
    else if (DSTSEL == 1) { C = (blockIdx.y == 0) ? g_xl1 : g_xr1; ldc = 128; }
    else                  { C = (blockIdx.y == 0) ? g_xl2 : g_xr2; ldc = 64; }

    __shared__ __nv_bfloat16 Ah[128][SSTR];
    __shared__ __nv_bfloat16 Al[128][SSTR];
    __shared__ __nv_bfloat16 Bh[BN][SSTR];   // [col][k]
    __shared__ __nv_bfloat16 Bl[BN][SSTR];

    int tid  = threadIdx.x;
    int lane = tid & 31;
    int ww   = tid >> 5;
    int bm   = blockIdx.x * 128;
    int wm0  = (ww & 1) * 64;
    int wn0  = (ww >> 1) * (BN / 4);
    int tg   = lane & 3;
    int gid  = lane >> 2;

    float acc[4][NF][4] = {};

#pragma unroll 1
    for (int k0 = 0; k0 < K; k0 += 32) {
        // A fill: 128 rows x 32 k; thread = (row, 16-k half) = 2 uint4 per array
        {
            int row  = tid >> 1;
            int half = (tid & 1) * 16;
            int arow = bm + row; if (arow >= M) arow = M - 1;
            size_t off = (size_t)arow * K + k0 + half;
            *(uint4*)&Ah[row][half]     = *(const uint4*)(Agh + off);
            *(uint4*)&Ah[row][half + 8] = *(const uint4*)(Agh + off + 8);
            *(uint4*)&Al[row][half]     = *(const uint4*)(Agl + off);
            *(uint4*)&Al[row][half + 8] = *(const uint4*)(Agl + off + 8);
        }
        // B fill: BN cols x 32 k; chunk = (col, 16-k half) = 2 uint4 per array
        {
#pragma unroll
            for (int q = tid; q < BN * 2; q += 256) {
                int col  = q >> 1;
                int half = (q & 1) * 16;
                size_t off = (size_t)col * K + k0 + half;
                *(uint4*)&Bh[col][half]     = *(const uint4*)(Bgh + off);
                *(uint4*)&Bh[col][half + 8] = *(const uint4*)(Bgh + off + 8);
                *(uint4*)&Bl[col][half]     = *(const uint4*)(Bgl + off);
                *(uint4*)&Bl[col][half + 8] = *(const uint4*)(Bgl + off + 8);
            }
        }
        __syncthreads();

#pragma unroll
        for (int s = 0; s < 2; s++) {
            int kb = s * 16;
            uint32_t ah[4][4], al[4][4];
#pragma unroll
            for (int im = 0; im < 4; im++) {
                int mr = wm0 + im * 16 + gid;
                ah[im][0] = *(const uint32_t*)&Ah[mr][kb + 2 * tg];
                ah[im][1] = *(const uint32_t*)&Ah[mr + 8][kb + 2 * tg];
                ah[im][2] = *(const uint32_t*)&Ah[mr][kb + 2 * tg + 8];
                ah[im][3] = *(const uint32_t*)&Ah[mr + 8][kb + 2 * tg + 8];
                al[im][0] = *(const uint32_t*)&Al[mr][kb + 2 * tg];
                al[im][1] = *(const uint32_t*)&Al[mr + 8][kb + 2 * tg];
                al[im][2] = *(const uint32_t*)&Al[mr][kb + 2 * tg + 8];
                al[im][3] = *(const uint32_t*)&Al[mr + 8][kb + 2 * tg + 8];
            }
            uint32_t bh[NF][2], bl[NF][2];
#pragma unroll
            for (int in = 0; in < NF; in++) {
                int nc = wn0 + in * 8 + gid;
                bh[in][0] = *(const uint32_t*)&Bh[nc][kb + 2 * tg];
                bh[in][1] = *(const uint32_t*)&Bh[nc][kb + 2 * tg + 8];
                bl[in][0] = *(const uint32_t*)&Bl[nc][kb + 2 * tg];
                bl[in][1] = *(const uint32_t*)&Bl[nc][kb + 2 * tg + 8];
            }
#pragma unroll
            for (int im = 0; im < 4; im++)
#pragma unroll
                for (int in = 0; in < NF; in++) {
                    mma_bf16(acc[im][in], ah[im], bh[in]);
                    mma_bf16(acc[im][in], ah[im], bl[in]);
                    mma_bf16(acc[im][in], al[im], bh[in]);
                }
        }
        __syncthreads();
    }

#pragma unroll
    for (int im = 0; im < 4; im++) {
        int r0 = bm + wm0 + im * 16 + gid;
#pragma unroll
        for (int in = 0; in < NF; in++) {
            int cc = wn0 + in * 8 + 2 * tg;
            float bx = bias[cc], by = bias[cc + 1];
            if (r0 < M) {
                float2 v = make_float2(acc[im][in][0] + bx, acc[im][in][1] + by);
                if (ACT) { v.x = elu1(v.x); v.y = elu1(v.y); }
                *(float2*)(C + (size_t)r0 * ldc + cc) = v;
            }
            if (r0 + 8 < M) {
                float2 v = make_float2(acc[im][in][2] + bx, acc[im][in][3] + by);
                if (ACT) { v.x = elu1(v.x); v.y = elu1(v.y); }
                *(float2*)(C + (size_t)(r0 + 8) * ldc + cc) = v;
            }
        }
    }
}

// --------- layer 1 edge phase, CSR, warp per node; writes h1 as bf16 hi/lo ---------
__global__ void k_edge1_csr(const float* __restrict__ att,
                            const float* __restrict__ bias, int N) {
    int gt = blockIdx.x * blockDim.x + threadIdx.x;
    int lane = gt & 31, w = gt >> 5;
    if (w >= N) return;

    float4 attr = *(const float4*)(att + lane * 4);
    float4 b = *(const float4*)(g_xr1 + (size_t)w * 128 + lane * 4);

    int beg = g_rowptr[w], end = g_rowptr[w + 1];
    float4 acc = make_float4(0.f, 0.f, 0.f, 0.f);
    float den = 0.f;

    int s = g_esrc[beg];
    float4 a = *(const float4*)(g_xl1 + (size_t)s * 128 + lane * 4);
    for (int p = beg; p < end; p++) {
        float4 ac = a;
        if (p + 1 < end) {
            s = g_esrc[p + 1];
            a = *(const float4*)(g_xl1 + (size_t)s * 128 + lane * 4);
        }
        float z0 = ac.x + b.x; z0 = z0 > 0.f ? z0 : 0.2f * z0;
        float z1 = ac.y + b.y; z1 = z1 > 0.f ? z1 : 0.2f * z1;
        float z2 = ac.z + b.z; z2 = z2 > 0.f ? z2 : 0.2f * z2;
        float z3 = ac.w + b.w; z3 = z3 > 0.f ? z3 : 0.2f * z3;
        float part = attr.x * z0 + attr.y * z1 + attr.z * z2 + attr.w * z3;
        part += __shfl_xor_sync(0xffffffffu, part, 1);
        part += __shfl_xor_sync(0xffffffffu, part, 2);
        float ex = __expf(part);
        den += ex;
        acc.x += ac.x * ex; acc.y += ac.y * ex;
        acc.z += ac.z * ex; acc.w += ac.w * ex;
    }

    float inv = 1.f / den;
    int c = lane * 4;
    float o[4];
    o[0] = elu1(acc.x * inv + bias[c + 0]);
    o[1] = elu1(acc.y * inv + bias[c + 1]);
    o[2] = elu1(acc.z * inv + bias[c + 2]);
    o[3] = elu1(acc.w * inv + bias[c + 3]);
    __nv_bfloat16 h[4], l[4];
#pragma unroll
    for (int q = 0; q < 4; q++) split_bf(o[q], h[q], l[q]);
    *(uint2*)(g_h1h + (size_t)w * 128 + c) = *(uint2*)h;
    *(uint2*)(g_h1l + (size_t)w * 128 + c) = *(uint2*)l;
}

// --------- layer 2 edge pass, CSR, warp per node; writes h2 as bf16 hi/lo ---------
__global__ void k_edge2_csr(const float* __restrict__ att,
                            const float* __restrict__ bias, int N) {
    int gt = blockIdx.x * blockDim.x + threadIdx.x;
    int lane = gt & 31, w = gt >> 5;
    if (w >= N) return;

    float2 attr = *(const float2*)(att + lane * 2);
    float2 b = *(const float2*)(g_xr2 + (size_t)w * 64 + lane * 2);

    int beg = g_rowptr[w], end = g_rowptr[w + 1];
    float2 acc = make_float2(0.f, 0.f);
    float den = 0.f;

    int s = g_esrc[beg];
    float2 a = *(const float2*)(g_xl2 + (size_t)s * 64 + lane * 2);
    for (int p = beg; p < end; p++) {
        float2 ac = a;
        if (p + 1 < end) {
            s = g_esrc[p + 1];
            a = *(const float2*)(g_xl2 + (size_t)s * 64 + lane * 2);
        }
        float z0 = ac.x + b.x; z0 = z0 > 0.f ? z0 : 0.2f * z0;
        float z1 = ac.y + b.y; z1 = z1 > 0.f ? z1 : 0.2f * z1;
        float part = attr.x * z0 + attr.y * z1;
        part += __shfl_xor_sync(0xffffffffu, part, 1);
        part += __shfl_xor_sync(0xffffffffu, part, 2);
        part += __shfl_xor_sync(0xffffffffu, part, 4);
        part += __shfl_xor_sync(0xffffffffu, part, 8);
        part += __shfl_xor_sync(0xffffffffu, part, 16);
        float ex = __expf(part);
        den += ex;
        acc.x += ac.x * ex; acc.y += ac.y * ex;
    }

    float inv = 1.f / den;
    int c = lane * 2;
    float o0 = elu1(acc.x * inv + bias[c + 0]);
    float o1 = elu1(acc.y * inv + bias[c + 1]);
    __nv_bfloat16 h[2], l[2];
    split_bf(o0, h[0], l[0]);
    split_bf(o1, h[1], l[1]);
    *(uint32_t*)(g_h2h + (size_t)w * 64 + c) = *(uint32_t*)h;
    *(uint32_t*)(g_h2l + (size_t)w * 64 + c) = *(uint32_t*)l;
}

// ------------------------- launch -------------------------
static inline int cdiv(int a, int b) { return (a + b - 1) / b; }

extern "C" void kernel_launch(void* const* d_in, const int* in_sizes, int n_in,
                              void* d_out, int out_size) {
    const float* x     = (const float*)d_in[0];
    const int*   ei    = (const int*)d_in[1];
    const float* Wl1   = (const float*)d_in[2];
    const float* bl1   = (const float*)d_in[3];
    const float* Wr1   = (const float*)d_in[4];
    const float* br1   = (const float*)d_in[5];
    const float* att1  = (const float*)d_in[6];
    const float* bias1 = (const float*)d_in[7];
    const float* Wl2   = (const float*)d_in[8];
    const float* bl2   = (const float*)d_in[9];
    const float* Wr2   = (const float*)d_in[10];
    const float* br2   = (const float*)d_in[11];
    const float* att2  = (const float*)d_in[12];
    const float* bias2 = (const float*)d_in[13];
    const float* Wlin  = (const float*)d_in[14];
    const float* blin  = (const float*)d_in[15];

    int N = in_sizes[0] / 128;
    int E = in_sizes[1] / 2;
    int Etot = E + N;
    int NB = cdiv(N, 256);

    // #1, #2: precompute bf16 hi/lo inputs and transposed weights
    k_cvtA<<<cdiv(N * 128, 1024), 256>>>(x, N * 128);
    k_cvtW<<<224, 256>>>(Wl1, Wr1, Wl2, Wr2, Wlin);

    k_initdeg<<<NB, 256>>>(N);                           // #3

    // #4 (profiled slot): layer-1 dual GEMM
    dim3 g1(cdiv(N, 128), 2);
    k_gemm_bf<128, 128, 0, 0, 1, 1><<<g1, 256>>>(bl1, br1, nullptr, N);

    // CSR build (rest)
    k_hist<<<cdiv(E, 256), 256>>>(ei, E);                // #5
    k_scanblk<<<NB, 256>>>(N);                           // #6
    k_scantop<<<1, 256>>>(NB);                           // #7
    k_finalize<<<NB, 256>>>(N, Etot);                    // #8
    k_scatter<<<cdiv(E, 256), 256>>>(ei, E);             // #9

    // layer 1 edge phase
    k_edge1_csr<<<cdiv(N * 32, 256), 256>>>(att1, bias1, N);

    // layer 2
    dim3 g2(cdiv(N, 128), 2);
    k_gemm_bf<128, 64, 0, 1, 2, 2><<<g2, 256>>>(bl2, br2, nullptr, N);
    k_edge2_csr<<<cdiv(N * 32, 256), 256>>>(att2, bias2, N);

    // final linear + ELU -> d_out [N,128]
    dim3 g3(cdiv(N, 128), 1);
    k_gemm_bf<64, 128, 1, 2, 3, 0><<<g3, 256>>>(blin, blin, (float*)d_out, N);
}

// round 11
// speedup vs baseline: 1.2420x; 1.0020x over previous
#include <cuda_runtime.h>
#include <cuda_bf16.h>
#include <cstdint>

#define NMAX    50048
#define EMAX    800000
#define ETOTMAX (NMAX + EMAX)
#define NBLKMAX 256

// ------------------------- scratch (device globals) -------------------------
__device__ __align__(16) float g_xl1[NMAX * 128];
__device__ __align__(16) float g_xr1[NMAX * 128];
__device__ __align__(16) float g_xl2[NMAX * 64];
__device__ __align__(16) float g_xr2[NMAX * 64];
// bf16 hi/lo GEMM inputs, PERMUTED k-order within each row (see permk)
__device__ __align__(16) __nv_bfloat16 g_xh [NMAX * 128];
__device__ __align__(16) __nv_bfloat16 g_xlo[NMAX * 128];
__device__ __align__(16) __nv_bfloat16 g_h1h[NMAX * 128];
__device__ __align__(16) __nv_bfloat16 g_h1l[NMAX * 128];
__device__ __align__(16) __nv_bfloat16 g_h2h[NMAX * 64];
__device__ __align__(16) __nv_bfloat16 g_h2l[NMAX * 64];
// weights, transposed to [col][k] with permuted k, bf16 hi/lo
__device__ __align__(16) __nv_bfloat16 g_w1h[2 * 128 * 128];
__device__ __align__(16) __nv_bfloat16 g_w1l[2 * 128 * 128];
__device__ __align__(16) __nv_bfloat16 g_w2h[2 * 64 * 128];
__device__ __align__(16) __nv_bfloat16 g_w2l[2 * 64 * 128];
__device__ __align__(16) __nv_bfloat16 g_w3h[128 * 64];
__device__ __align__(16) __nv_bfloat16 g_w3l[128 * 64];
// CSR
__device__ __align__(16) int g_deg[NMAX];
__device__ __align__(16) int g_pre[NMAX];
__device__ __align__(16) int g_bsum[NBLKMAX];
__device__ __align__(16) int g_rowptr[NMAX + 1];
__device__ __align__(16) int g_cursor[NMAX];
__device__ __align__(16) int g_esrc[ETOTMAX];

// ------------------------- helpers -------------------------
__device__ __forceinline__ float elu1(float v) { return v > 0.f ? v : expm1f(v); }

__device__ __forceinline__ void split_bf(float v, __nv_bfloat16& h, __nv_bfloat16& l) {
    h = __float2bfloat16_rn(v);
    l = __float2bfloat16_rn(v - __bfloat162float(h));
}

// permuted element index within a row: per 32-elem chunk, word j (2 elems) goes to
// slot pos(j) = (j%4)*4 + j/4, so a fragment thread's 4 words are one uint4.
__device__ __forceinline__ int permk(int k) {
    int chunk = k >> 5;
    int j = (k & 31) >> 1;
    int lo = k & 1;
    int pos = (j & 3) * 4 + (j >> 2);
    return chunk * 32 + pos * 2 + lo;
}

__device__ __forceinline__ void mma_bf16(float* c, const uint32_t* a, const uint32_t* b) {
    asm volatile(
        "mma.sync.aligned.m16n8k16.row.col.f32.bf16.bf16.f32 "
        "{%0,%1,%2,%3}, {%4,%5,%6,%7}, {%8,%9}, {%0,%1,%2,%3};\n"
        : "+f"(c[0]), "+f"(c[1]), "+f"(c[2]), "+f"(c[3])
        : "r"(a[0]), "r"(a[1]), "r"(a[2]), "r"(a[3]), "r"(b[0]), "r"(b[1]));
}

// ------------------------- conversions -------------------------
__global__ void k_cvtA(const float* __restrict__ x, int n) {
    int i = (blockIdx.x * blockDim.x + threadIdx.x) * 4;   // 4 elems = words j, j+1
    if (i < n) {
        float4 v = *(const float4*)(x + i);
        __nv_bfloat16 h[4], l[4];
        split_bf(v.x, h[0], l[0]); split_bf(v.y, h[1], l[1]);
        split_bf(v.z, h[2], l[2]); split_bf(v.w, h[3], l[3]);
        int base = i & ~127;
        int p0 = base + permk(i & 127);
        int p1 = base + permk((i & 127) + 2);
        *(uint32_t*)(g_xh  + p0) = *(uint32_t*)&h[0];
        *(uint32_t*)(g_xh  + p1) = *(uint32_t*)&h[2];
        *(uint32_t*)(g_xlo + p0) = *(uint32_t*)&l[0];
        *(uint32_t*)(g_xlo + p1) = *(uint32_t*)&l[2];
    }
}

// transpose + split + permute all weights: L1 (2x 128x128), L2 (2x 128x64), lin (64x128)
__global__ void k_cvtW(const float* __restrict__ Wl1, const float* __restrict__ Wr1,
                       const float* __restrict__ Wl2, const float* __restrict__ Wr2,
                       const float* __restrict__ Wlin) {
    int i = blockIdx.x * blockDim.x + threadIdx.x;   // 57344 total
    if (i < 32768) {                                  // L1: m, col(128), k(128)
        int m = i >> 14, r = i & 16383, c = r >> 7, k = r & 127;
        const float* W = m ? Wr1 : Wl1;
        int o = (m << 14) + (c << 7) + permk(k);
        split_bf(W[k * 128 + c], g_w1h[o], g_w1l[o]);
    } else if (i < 49152) {                           // L2: m, col(64), k(128)
        int j = i - 32768;
        int m = j >> 13, r = j & 8191, c = r >> 7, k = r & 127;
        const float* W = m ? Wr2 : Wl2;
        int o = (m << 13) + (c << 7) + permk(k);
        split_bf(W[k * 64 + c], g_w2h[o], g_w2l[o]);
    } else {                                          // lin: col(128), k(64)
        int j = i - 49152;
        int c = j >> 6, k = j & 63;
        int o = (c << 6) + permk(k);
        split_bf(Wlin[k * 128 + c], g_w3h[o], g_w3l[o]);
    }
}

// ------------------------- CSR build -------------------------
__global__ void k_initdeg(int N) {
    int i = blockIdx.x * blockDim.x + threadIdx.x;
    if (i < N) g_deg[i] = 1;              // self-loop
}
__global__ void k_hist(const int* __restrict__ ei, int E) {
    int i = blockIdx.x * blockDim.x + threadIdx.x;
    if (i < E) atomicAdd(&g_deg[ei[E + i]], 1);
}
__global__ void k_scanblk(int N) {
    __shared__ int sh[256];
    int i = blockIdx.x * 256 + threadIdx.x;
    int v = (i < N) ? g_deg[i] : 0;
    sh[threadIdx.x] = v;
    __syncthreads();
    for (int off = 1; off < 256; off <<= 1) {
        int t = (threadIdx.x >= off) ? sh[threadIdx.x - off] : 0;
        __syncthreads();
        sh[threadIdx.x] += t;
        __syncthreads();
    }
    if (i < N) g_pre[i] = sh[threadIdx.x] - v;   // exclusive
    if (threadIdx.x == 255) g_bsum[blockIdx.x] = sh[255];
}
__global__ void k_scantop(int NB) {
    __shared__ int sh[256];
    int v = (threadIdx.x < NB) ? g_bsum[threadIdx.x] : 0;
    sh[threadIdx.x] = v;
    __syncthreads();
    for (int off = 1; off < 256; off <<= 1) {
        int t = (threadIdx.x >= off) ? sh[threadIdx.x - off] : 0;
        __syncthreads();
        sh[threadIdx.x] += t;
        __syncthreads();
    }
    if (threadIdx.x < NB) g_bsum[threadIdx.x] = sh[threadIdx.x] - v;  // exclusive
}
__global__ void k_finalize(int N, int Etot) {
    int i = blockIdx.x * blockDim.x + threadIdx.x;
    if (i < N) {
        int rp = g_pre[i] + g_bsum[i >> 8];
        g_rowptr[i] = rp;
        g_cursor[i] = rp + 1;
        g_esrc[rp] = i;                   // self-loop occupies first slot
        if (i == 0) g_rowptr[N] = Etot;
    }
}
__global__ void k_scatter(const int* __restrict__ ei, int E) {
    int i = blockIdx.x * blockDim.x + threadIdx.x;
    if (i < E) {
        int d = ei[E + i];
        int slot = atomicAdd(&g_cursor[d], 1);
        g_esrc[slot] = ei[i];
    }
}

// --------------- bf16x3-split tensor GEMM, permuted-k inputs, LDS.128 frags ---------------
// C[M,BN] = A[M,K] @ W[K,BN] + bias.  BM=128, BK=32, 256 thr = 8 warps (2m x 4n).
// SRC: 0 = g_xh/g_xlo (K=128), 1 = g_h1h/g_h1l (K=128), 2 = g_h2h/g_h2l (K=64).
// WSEL: 1 = g_w1 (+y*16384), 2 = g_w2 (+y*8192), 3 = g_w3.
// DSTSEL: 0 = Carg (ldc=BN), 1 = y-sel (xl1,xr1) ldc=128, 2 = y-sel (xl2,xr2) ldc=64.
template <int K, int BN, int ACT, int SRC, int WSEL, int DSTSEL>
__global__ __launch_bounds__(256, 2) void k_gemm_bf(const float* __restrict__ b0,
                                                    const float* __restrict__ b1,
                                                    float* __restrict__ Carg, int M) {
    const int NF = BN / 32;
    const int KU4 = K / 8;                    // uint4 per global row

    const __nv_bfloat16* Agh = (SRC == 0) ? g_xh : (SRC == 1 ? g_h1h : g_h2h);
    const __nv_bfloat16* Agl = (SRC == 0) ? g_xlo : (SRC == 1 ? g_h1l : g_h2l);
    const __nv_bfloat16* Bgh = (WSEL == 1) ? g_w1h + blockIdx.y * 16384
                              : (WSEL == 2) ? g_w2h + blockIdx.y * 8192 : g_w3h;
    const __nv_bfloat16* Bgl = (WSEL == 1) ? g_w1l + blockIdx.y * 16384
                              : (WSEL == 2) ? g_w2l + blockIdx.y * 8192 : g_w3l;
    const float* bias = (blockIdx.y == 0) ? b0 : b1;
    float* C;
    int ldc;
    if (DSTSEL == 0)      { C = Carg; ldc = BN; }
    else if (DSTSEL == 1) { C = (blockIdx.y == 0) ? g_xl1 : g_xr1; ldc = 128; }
    else                  { C = (blockIdx.y == 0) ? g_xl2 : g_xr2; ldc = 64; }

    // rows of exactly 64B (32 bf16): conflict-free LDS.128 fragment loads
    __shared__ __nv_bfloat16 Ah[128][32];
    __shared__ __nv_bfloat16 Al[128][32];
    __shared__ __nv_bfloat16 Bh[BN][32];
    __shared__ __nv_bfloat16 Bl[BN][32];

    int tid  = threadIdx.x;
    int lane = tid & 31;
    int ww   = tid >> 5;
    int bm   = blockIdx.x * 128;
    int wm0  = (ww & 1) * 64;
    int wn0  = (ww >> 1) * (BN / 4);
    int tg   = lane & 3;
    int gid  = lane >> 2;

    float acc[4][NF][4] = {};

#pragma unroll 1
    for (int k0 = 0; k0 < K; k0 += 32) {
        int ck4 = (k0 >> 5) * 4;              // uint4 offset of this k-chunk
        // A fill: thread = (row, 32B half); 2+2 uint4 copies
        {
            int row = tid >> 1, q = (tid & 1) * 2;
            int arow = bm + row; if (arow >= M) arow = M - 1;
            const uint4* ph = (const uint4*)Agh + (size_t)arow * KU4 + ck4;
            const uint4* pl = (const uint4*)Agl + (size_t)arow * KU4 + ck4;
            uint4* sh = (uint4*)&Ah[row][0];
            uint4* sl = (uint4*)&Al[row][0];
            sh[q] = ph[q]; sh[q + 1] = ph[q + 1];
            sl[q] = pl[q]; sl[q + 1] = pl[q + 1];
        }
        // B fill: BN*4 uint4 per array
        {
#pragma unroll
            for (int q = tid; q < BN * 4; q += 256) {
                int col = q >> 2, part = q & 3;
                ((uint4*)&Bh[col][0])[part] =
                    ((const uint4*)Bgh)[(size_t)col * KU4 + ck4 + part];
                ((uint4*)&Bl[col][0])[part] =
                    ((const uint4*)Bgl)[(size_t)col * KU4 + ck4 + part];
            }
        }
        __syncthreads();

        // B fragments for the whole k-chunk (both k16 steps): 2*NF LDS.128
        uint4 vbh[NF], vbl[NF];
#pragma unroll
        for (int in = 0; in < NF; in++) {
            int nc = wn0 + in * 8 + gid;
            vbh[in] = *(const uint4*)&Bh[nc][tg * 8];
            vbl[in] = *(const uint4*)&Bl[nc][tg * 8];
        }

#pragma unroll
        for (int im = 0; im < 4; im++) {
            int mr = wm0 + im * 16 + gid;
            uint4 vh = *(const uint4*)&Ah[mr][tg * 8];
            uint4 uh = *(const uint4*)&Ah[mr + 8][tg * 8];
            uint4 vl = *(const uint4*)&Al[mr][tg * 8];
            uint4 ul = *(const uint4*)&Al[mr + 8][tg * 8];
            uint32_t ah0[4] = {vh.x, uh.x, vh.y, uh.y};   // s = 0
            uint32_t ah1[4] = {vh.z, uh.z, vh.w, uh.w};   // s = 1
            uint32_t al0[4] = {vl.x, ul.x, vl.y, ul.y};
            uint32_t al1[4] = {vl.z, ul.z, vl.w, ul.w};
#pragma unroll
            for (int in = 0; in < NF; in++) {
                uint32_t bh0[2] = {vbh[in].x, vbh[in].y};
                uint32_t bh1[2] = {vbh[in].z, vbh[in].w};
                uint32_t bl0[2] = {vbl[in].x, vbl[in].y};
                uint32_t bl1[2] = {vbl[in].z, vbl[in].w};
                mma_bf16(acc[im][in], ah0, bh0);
                mma_bf16(acc[im][in], ah0, bl0);
                mma_bf16(acc[im][in], al0, bh0);
                mma_bf16(acc[im][in], ah1, bh1);
                mma_bf16(acc[im][in], ah1, bl1);
                mma_bf16(acc[im][in], al1, bh1);
            }
        }
        __syncthreads();
    }

#pragma unroll
    for (int im = 0; im < 4; im++) {
        int r0 = bm + wm0 + im * 16 + gid;
#pragma unroll
        for (int in = 0; in < NF; in++) {
            int cc = wn0 + in * 8 + 2 * tg;
            float bx = bias[cc], by = bias[cc + 1];
            if (r0 < M) {
                float2 v = make_float2(acc[im][in][0] + bx, acc[im][in][1] + by);
                if (ACT) { v.x = elu1(v.x); v.y = elu1(v.y); }
                *(float2*)(C + (size_t)r0 * ldc + cc) = v;
            }
            if (r0 + 8 < M) {
                float2 v = make_float2(acc[im][in][2] + bx, acc[im][in][3] + by);
                if (ACT) { v.x = elu1(v.x); v.y = elu1(v.y); }
                *(float2*)(C + (size_t)(r0 + 8) * ldc + cc) = v;
            }
        }
    }
}

// --------- layer 1 edge phase, CSR, warp per node; writes h1 as permuted bf16 hi/lo ---------
__global__ void k_edge1_csr(const float* __restrict__ att,
                            const float* __restrict__ bias, int N) {
    int gt = blockIdx.x * blockDim.x + threadIdx.x;
    int lane = gt & 31, w = gt >> 5;
    if (w >= N) return;

    float4 attr = *(const float4*)(att + lane * 4);
    float4 b = *(const float4*)(g_xr1 + (size_t)w * 128 + lane * 4);

    int beg = g_rowptr[w], end = g_rowptr[w + 1];
    float4 acc = make_float4(0.f, 0.f, 0.f, 0.f);
    float den = 0.f;

    int s = g_esrc[beg];
    float4 a = *(const float4*)(g_xl1 + (size_t)s * 128 + lane * 4);
    for (int p = beg; p < end; p++) {
        float4 ac = a;
        if (p + 1 < end) {
            s = g_esrc[p + 1];
            a = *(const float4*)(g_xl1 + (size_t)s * 128 + lane * 4);
        }
        float z0 = ac.x + b.x; z0 = z0 > 0.f ? z0 : 0.2f * z0;
        float z1 = ac.y + b.y; z1 = z1 > 0.f ? z1 : 0.2f * z1;
        float z2 = ac.z + b.z; z2 = z2 > 0.f ? z2 : 0.2f * z2;
        float z3 = ac.w + b.w; z3 = z3 > 0.f ? z3 : 0.2f * z3;
        float part = attr.x * z0 + attr.y * z1 + attr.z * z2 + attr.w * z3;
        part += __shfl_xor_sync(0xffffffffu, part, 1);
        part += __shfl_xor_sync(0xffffffffu, part, 2);
        float ex = __expf(part);
        den += ex;
        acc.x += ac.x * ex; acc.y += ac.y * ex;
        acc.z += ac.z * ex; acc.w += ac.w * ex;
    }

    float inv = 1.f / den;
    int c = lane * 4;
    float o[4];
    o[0] = elu1(acc.x * inv + bias[c + 0]);
    o[1] = elu1(acc.y * inv + bias[c + 1]);
    o[2] = elu1(acc.z * inv + bias[c + 2]);
    o[3] = elu1(acc.w * inv + bias[c + 3]);
    __nv_bfloat16 h[4], l[4];
#pragma unroll
    for (int q = 0; q < 4; q++) split_bf(o[q], h[q], l[q]);
    size_t base = (size_t)w * 128;
    int p0 = permk(c), p1 = permk(c + 2);
    *(uint32_t*)(g_h1h + base + p0) = *(uint32_t*)&h[0];
    *(uint32_t*)(g_h1h + base + p1) = *(uint32_t*)&h[2];
    *(uint32_t*)(g_h1l + base + p0) = *(uint32_t*)&l[0];
    *(uint32_t*)(g_h1l + base + p1) = *(uint32_t*)&l[2];
}

// --------- layer 2 edge pass, CSR, warp per node; writes h2 as permuted bf16 hi/lo ---------
__global__ void k_edge2_csr(const float* __restrict__ att,
                            const float* __restrict__ bias, int N) {
    int gt = blockIdx.x * blockDim.x + threadIdx.x;
    int lane = gt & 31, w = gt >> 5;
    if (w >= N) return;

    float2 attr = *(const float2*)(att + lane * 2);
    float2 b = *(const float2*)(g_xr2 + (size_t)w * 64 + lane * 2);

    int beg = g_rowptr[w], end = g_rowptr[w + 1];
    float2 acc = make_float2(0.f, 0.f);
    float den = 0.f;

    int s = g_esrc[beg];
    float2 a = *(const float2*)(g_xl2 + (size_t)s * 64 + lane * 2);
    for (int p = beg; p < end; p++) {
        float2 ac = a;
        if (p + 1 < end) {
            s = g_esrc[p + 1];
            a = *(const float2*)(g_xl2 + (size_t)s * 64 + lane * 2);
        }
        float z0 = ac.x + b.x; z0 = z0 > 0.f ? z0 : 0.2f * z0;
        float z1 = ac.y + b.y; z1 = z1 > 0.f ? z1 : 0.2f * z1;
        float part = attr.x * z0 + attr.y * z1;
        part += __shfl_xor_sync(0xffffffffu, part, 1);
        part += __shfl_xor_sync(0xffffffffu, part, 2);
        part += __shfl_xor_sync(0xffffffffu, part, 4);
        part += __shfl_xor_sync(0xffffffffu, part, 8);
        part += __shfl_xor_sync(0xffffffffu, part, 16);
        float ex = __expf(part);
        den += ex;
        acc.x += ac.x * ex; acc.y += ac.y * ex;
    }

    float inv = 1.f / den;
    int c = lane * 2;
    float o0 = elu1(acc.x * inv + bias[c + 0]);
    float o1 = elu1(acc.y * inv + bias[c + 1]);
    __nv_bfloat16 h[2], l[2];
    split_bf(o0, h[0], l[0]);
    split_bf(o1, h[1], l[1]);
    size_t base = (size_t)w * 64;
    int p0 = permk(c);
    *(uint32_t*)(g_h2h + base + p0) = *(uint32_t*)&h[0];
    *(uint32_t*)(g_h2l + base + p0) = *(uint32_t*)&l[0];
}

// ------------------------- launch -------------------------
static inline int cdiv(int a, int b) { return (a + b - 1) / b; }

extern "C" void kernel_launch(void* const* d_in, const int* in_sizes, int n_in,
                              void* d_out, int out_size) {
    const float* x     = (const float*)d_in[0];
    const int*   ei    = (const int*)d_in[1];
    const float* Wl1   = (const float*)d_in[2];
    const float* bl1   = (const float*)d_in[3];
    const float* Wr1   = (const float*)d_in[4];
    const float* br1   = (const float*)d_in[5];
    const float* att1  = (const float*)d_in[6];
    const float* bias1 = (const float*)d_in[7];
    const float* Wl2   = (const float*)d_in[8];
    const float* bl2   = (const float*)d_in[9];
    const float* Wr2   = (const float*)d_in[10];
    const float* br2   = (const float*)d_in[11];
    const float* att2  = (const float*)d_in[12];
    const float* bias2 = (const float*)d_in[13];
    const float* Wlin  = (const float*)d_in[14];
    const float* blin  = (const float*)d_in[15];

    int N = in_sizes[0] / 128;
    int E = in_sizes[1] / 2;
    int Etot = E + N;
    int NB = cdiv(N, 256);

    // precompute bf16 hi/lo (permuted) inputs and transposed weights
    k_cvtA<<<cdiv(N * 128, 1024), 256>>>(x, N * 128);
    k_cvtW<<<224, 256>>>(Wl1, Wr1, Wl2, Wr2, Wlin);

    k_initdeg<<<NB, 256>>>(N);

    // layer-1 dual GEMM (profiled slot #4)
    dim3 g1(cdiv(N, 128), 2);
    k_gemm_bf<128, 128, 0, 0, 1, 1><<<g1, 256>>>(bl1, br1, nullptr, N);

    // CSR build (rest)
    k_hist<<<cdiv(E, 256), 256>>>(ei, E);
    k_scanblk<<<NB, 256>>>(N);
    k_scantop<<<1, 256>>>(NB);
    k_finalize<<<NB, 256>>>(N, Etot);
    k_scatter<<<cdiv(E, 256), 256>>>(ei, E);

    // layer 1 edge phase
    k_edge1_csr<<<cdiv(N * 32, 256), 256>>>(att1, bias1, N);

    // layer 2
    dim3 g2(cdiv(N, 128), 2);
    k_gemm_bf<128, 64, 0, 1, 2, 2><<<g2, 256>>>(bl2, br2, nullptr, N);
    k_edge2_csr<<<cdiv(N * 32, 256), 256>>>(att2, bias2, N);

    // final linear + ELU -> d_out [N,128]
    dim3 g3(cdiv(N, 128), 1);
    k_gemm_bf<64, 128, 1, 2, 3, 0><<<g3, 256>>>(blin, blin, (float*)d_out, N);
}

// round 12
// speedup vs baseline: 1.3072x; 1.0525x over previous
#include <cuda_runtime.h>
#include <cuda_bf16.h>
#include <cstdint>

#define NMAX    50048
#define EMAX    800000
#define ETOTMAX (NMAX + EMAX)
#define NBLKMAX 256

// ------------------------- scratch (device globals) -------------------------
__device__ __align__(16) float g_xl1[NMAX * 128];
__device__ __align__(16) float g_xr1[NMAX * 128];
__device__ __align__(16) float g_xl2[NMAX * 64];
__device__ __align__(16) float g_xr2[NMAX * 64];
// bf16 hi/lo GEMM inputs, PERMUTED k-order within each row (see permk)
__device__ __align__(16) __nv_bfloat16 g_xh [NMAX * 128];
__device__ __align__(16) __nv_bfloat16 g_xlo[NMAX * 128];
__device__ __align__(16) __nv_bfloat16 g_h1h[NMAX * 128];
__device__ __align__(16) __nv_bfloat16 g_h1l[NMAX * 128];
__device__ __align__(16) __nv_bfloat16 g_h2h[NMAX * 64];
__device__ __align__(16) __nv_bfloat16 g_h2l[NMAX * 64];
// weights, transposed to [col][k] with permuted k, bf16 hi/lo
__device__ __align__(16) __nv_bfloat16 g_w1h[2 * 128 * 128];
__device__ __align__(16) __nv_bfloat16 g_w1l[2 * 128 * 128];
__device__ __align__(16) __nv_bfloat16 g_w2h[2 * 64 * 128];
__device__ __align__(16) __nv_bfloat16 g_w2l[2 * 64 * 128];
__device__ __align__(16) __nv_bfloat16 g_w3h[128 * 64];
__device__ __align__(16) __nv_bfloat16 g_w3l[128 * 64];
// CSR
__device__ __align__(16) int g_deg[NMAX];
__device__ __align__(16) int g_pre[NMAX];
__device__ __align__(16) int g_bsum[NBLKMAX];
__device__ __align__(16) int g_rowptr[NMAX + 1];
__device__ __align__(16) int g_cursor[NMAX];
__device__ __align__(16) int g_esrc[ETOTMAX];

// ------------------------- helpers -------------------------
__device__ __forceinline__ float elu1(float v) { return v > 0.f ? v : expm1f(v); }

__device__ __forceinline__ void split_bf(float v, __nv_bfloat16& h, __nv_bfloat16& l) {
    h = __float2bfloat16_rn(v);
    l = __float2bfloat16_rn(v - __bfloat162float(h));
}

// permuted element index within a row: per 32-elem chunk, word j (2 elems) goes to
// slot pos(j) = (j%4)*4 + j/4, so a fragment thread's 4 words are one uint4.
__device__ __forceinline__ int permk(int k) {
    int chunk = k >> 5;
    int j = (k & 31) >> 1;
    int lo = k & 1;
    int pos = (j & 3) * 4 + (j >> 2);
    return chunk * 32 + pos * 2 + lo;
}

__device__ __forceinline__ void mma_bf16(float* c, const uint32_t* a, const uint32_t* b) {
    asm volatile(
        "mma.sync.aligned.m16n8k16.row.col.f32.bf16.bf16.f32 "
        "{%0,%1,%2,%3}, {%4,%5,%6,%7}, {%8,%9}, {%0,%1,%2,%3};\n"
        : "+f"(c[0]), "+f"(c[1]), "+f"(c[2]), "+f"(c[3])
        : "r"(a[0]), "r"(a[1]), "r"(a[2]), "r"(a[3]), "r"(b[0]), "r"(b[1]));
}

__device__ __forceinline__ uint32_t s2u(const void* p) {
    return (uint32_t)__cvta_generic_to_shared(p);
}
#define CP16(dst, src) \
    asm volatile("cp.async.cg.shared.global [%0], [%1], 16;\n" :: "r"(dst), "l"(src))
#define CP_COMMIT() asm volatile("cp.async.commit_group;\n" ::: "memory")
#define CP_WAIT0()  asm volatile("cp.async.wait_group 0;\n" ::: "memory")
#define CP_WAIT1()  asm volatile("cp.async.wait_group 1;\n" ::: "memory")

// ------------------------- conversions -------------------------
__global__ void k_cvtA(const float* __restrict__ x, int n) {
    int i = (blockIdx.x * blockDim.x + threadIdx.x) * 4;   // 4 elems = words j, j+1
    if (i < n) {
        float4 v = *(const float4*)(x + i);
        __nv_bfloat16 h[4], l[4];
        split_bf(v.x, h[0], l[0]); split_bf(v.y, h[1], l[1]);
        split_bf(v.z, h[2], l[2]); split_bf(v.w, h[3], l[3]);
        int base = i & ~127;
        int p0 = base + permk(i & 127);
        int p1 = base + permk((i & 127) + 2);
        *(uint32_t*)(g_xh  + p0) = *(uint32_t*)&h[0];
        *(uint32_t*)(g_xh  + p1) = *(uint32_t*)&h[2];
        *(uint32_t*)(g_xlo + p0) = *(uint32_t*)&l[0];
        *(uint32_t*)(g_xlo + p1) = *(uint32_t*)&l[2];
    }
}

// transpose + split + permute all weights: L1 (2x 128x128), L2 (2x 128x64), lin (64x128)
__global__ void k_cvtW(const float* __restrict__ Wl1, const float* __restrict__ Wr1,
                       const float* __restrict__ Wl2, const float* __restrict__ Wr2,
                       const float* __restrict__ Wlin) {
    int i = blockIdx.x * blockDim.x + threadIdx.x;   // 57344 total
    if (i < 32768) {                                  // L1: m, col(128), k(128)
        int m = i >> 14, r = i & 16383, c = r >> 7, k = r & 127;
        const float* W = m ? Wr1 : Wl1;
        int o = (m << 14) + (c << 7) + permk(k);
        split_bf(W[k * 128 + c], g_w1h[o], g_w1l[o]);
    } else if (i < 49152) {                           // L2: m, col(64), k(128)
        int j = i - 32768;
        int m = j >> 13, r = j & 8191, c = r >> 7, k = r & 127;
        const float* W = m ? Wr2 : Wl2;
        int o = (m << 13) + (c << 7) + permk(k);
        split_bf(W[k * 64 + c], g_w2h[o], g_w2l[o]);
    } else {                                          // lin: col(128), k(64)
        int j = i - 49152;
        int c = j >> 6, k = j & 63;
        int o = (c << 6) + permk(k);
        split_bf(Wlin[k * 128 + c], g_w3h[o], g_w3l[o]);
    }
}

// ------------------------- CSR build -------------------------
__global__ void k_initdeg(int N) {
    int i = blockIdx.x * blockDim.x + threadIdx.x;
    if (i < N) g_deg[i] = 1;              // self-loop
}
__global__ void k_hist(const int* __restrict__ ei, int E) {
    int i = blockIdx.x * blockDim.x + threadIdx.x;
    if (i < E) atomicAdd(&g_deg[ei[E + i]], 1);
}
__global__ void k_scanblk(int N) {
    __shared__ int sh[256];
    int i = blockIdx.x * 256 + threadIdx.x;
    int v = (i < N) ? g_deg[i] : 0;
    sh[threadIdx.x] = v;
    __syncthreads();
    for (int off = 1; off < 256; off <<= 1) {
        int t = (threadIdx.x >= off) ? sh[threadIdx.x - off] : 0;
        __syncthreads();
        sh[threadIdx.x] += t;
        __syncthreads();
    }
    if (i < N) g_pre[i] = sh[threadIdx.x] - v;   // exclusive
    if (threadIdx.x == 255) g_bsum[blockIdx.x] = sh[255];
}
__global__ void k_scantop(int NB) {
    __shared__ int sh[256];
    int v = (threadIdx.x < NB) ? g_bsum[threadIdx.x] : 0;
    sh[threadIdx.x] = v;
    __syncthreads();
    for (int off = 1; off < 256; off <<= 1) {
        int t = (threadIdx.x >= off) ? sh[threadIdx.x - off] : 0;
        __syncthreads();
        sh[threadIdx.x] += t;
        __syncthreads();
    }
    if (threadIdx.x < NB) g_bsum[threadIdx.x] = sh[threadIdx.x] - v;  // exclusive
}
__global__ void k_finalize(int N, int Etot) {
    int i = blockIdx.x * blockDim.x + threadIdx.x;
    if (i < N) {
        int rp = g_pre[i] + g_bsum[i >> 8];
        g_rowptr[i] = rp;
        g_cursor[i] = rp + 1;
        g_esrc[rp] = i;                   // self-loop occupies first slot
        if (i == 0) g_rowptr[N] = Etot;
    }
}
__global__ void k_scatter(const int* __restrict__ ei, int E) {
    int i = blockIdx.x * blockDim.x + threadIdx.x;
    if (i < E) {
        int d = ei[E + i];
        int slot = atomicAdd(&g_cursor[d], 1);
        g_esrc[slot] = ei[i];
    }
}

// ----- bf16x3-split tensor GEMM, permuted-k inputs, cp.async double-buffered -----
// C[M,BN] = A[M,K] @ W[K,BN] + bias.  BM=128, BK=32, 256 thr = 8 warps (2m x 4n).
// SRC: 0 = g_xh/g_xlo (K=128), 1 = g_h1h/g_h1l (K=128), 2 = g_h2h/g_h2l (K=64).
// WSEL: 1 = g_w1 (+y*16384), 2 = g_w2 (+y*8192), 3 = g_w3.
// DSTSEL: 0 = Carg (ldc=BN), 1 = y-sel (xl1,xr1) ldc=128, 2 = y-sel (xl2,xr2) ldc=64.
template <int K, int BN, int ACT, int SRC, int WSEL, int DSTSEL>
__global__ __launch_bounds__(256, 2) void k_gemm_bf(const float* __restrict__ b0,
                                                    const float* __restrict__ b1,
                                                    float* __restrict__ Carg, int M) {
    const int NF = BN / 32;
    const int KU4 = K / 8;                    // uint4 per global row
    const int NC = K / 32;                    // k-chunks

    const __nv_bfloat16* Agh = (SRC == 0) ? g_xh : (SRC == 1 ? g_h1h : g_h2h);
    const __nv_bfloat16* Agl = (SRC == 0) ? g_xlo : (SRC == 1 ? g_h1l : g_h2l);
    const __nv_bfloat16* Bgh = (WSEL == 1) ? g_w1h + blockIdx.y * 16384
                              : (WSEL == 2) ? g_w2h + blockIdx.y * 8192 : g_w3h;
    const __nv_bfloat16* Bgl = (WSEL == 1) ? g_w1l + blockIdx.y * 16384
                              : (WSEL == 2) ? g_w2l + blockIdx.y * 8192 : g_w3l;
    const float* bias = (blockIdx.y == 0) ? b0 : b1;
    float* C;
    int ldc;
    if (DSTSEL == 0)      { C = Carg; ldc = BN; }
    else if (DSTSEL == 1) { C = (blockIdx.y == 0) ? g_xl1 : g_xr1; ldc = 128; }
    else                  { C = (blockIdx.y == 0) ? g_xl2 : g_xr2; ldc = 64; }

    // double-buffered tiles; rows of exactly 64B -> conflict-free LDS.128 frags
    __shared__ __nv_bfloat16 Ah[2][128][32];
    __shared__ __nv_bfloat16 Al[2][128][32];
    __shared__ __nv_bfloat16 Bh[2][BN][32];
    __shared__ __nv_bfloat16 Bl[2][BN][32];

    int tid  = threadIdx.x;
    int lane = tid & 31;
    int ww   = tid >> 5;
    int bm   = blockIdx.x * 128;
    int wm0  = (ww & 1) * 64;
    int wn0  = (ww >> 1) * (BN / 4);
    int tg   = lane & 3;
    int gid  = lane >> 2;

    // per-thread fill coordinates (chunk-invariant)
    int fa_row = tid >> 1, fa_q = (tid & 1) * 2;
    int fa_arow = bm + fa_row; if (fa_arow >= M) fa_arow = M - 1;
    const uint4* fa_ph = (const uint4*)Agh + (size_t)fa_arow * KU4;
    const uint4* fa_pl = (const uint4*)Agl + (size_t)fa_arow * KU4;

    float acc[4][NF][4] = {};

    // -------- pipelined fill helper (macro-ish lambda) --------
    auto fill = [&](int buf, int c) {
        int ck4 = c * 4;
        CP16(s2u(&Ah[buf][fa_row][fa_q * 8]),       fa_ph + ck4 + fa_q);
        CP16(s2u(&Ah[buf][fa_row][(fa_q + 1) * 8]), fa_ph + ck4 + fa_q + 1);
        CP16(s2u(&Al[buf][fa_row][fa_q * 8]),       fa_pl + ck4 + fa_q);
        CP16(s2u(&Al[buf][fa_row][(fa_q + 1) * 8]), fa_pl + ck4 + fa_q + 1);
#pragma unroll
        for (int q = tid; q < BN * 4; q += 256) {
            int col = q >> 2, part = q & 3;
            CP16(s2u(&Bh[buf][col][part * 8]),
                 (const uint4*)Bgh + (size_t)col * KU4 + ck4 + part);
            CP16(s2u(&Bl[buf][col][part * 8]),
                 (const uint4*)Bgl + (size_t)col * KU4 + ck4 + part);
        }
    };

    fill(0, 0);
    CP_COMMIT();

#pragma unroll
    for (int c = 0; c < NC; c++) {
        int buf = c & 1;
        if (c + 1 < NC) { fill(buf ^ 1, c + 1); CP_COMMIT(); CP_WAIT1(); }
        else            { CP_WAIT0(); }
        __syncthreads();

        // B fragments for whole k-chunk (both k16 steps): 2*NF LDS.128
        uint4 vbh[NF], vbl[NF];
#pragma unroll
        for (int in = 0; in < NF; in++) {
            int nc = wn0 + in * 8 + gid;
            vbh[in] = *(const uint4*)&Bh[buf][nc][tg * 8];
            vbl[in] = *(const uint4*)&Bl[buf][nc][tg * 8];
        }

#pragma unroll
        for (int im = 0; im < 4; im++) {
            int mr = wm0 + im * 16 + gid;
            uint4 vh = *(const uint4*)&Ah[buf][mr][tg * 8];
            uint4 uh = *(const uint4*)&Ah[buf][mr + 8][tg * 8];
            uint4 vl = *(const uint4*)&Al[buf][mr][tg * 8];
            uint4 ul = *(const uint4*)&Al[buf][mr + 8][tg * 8];
            uint32_t ah0[4] = {vh.x, uh.x, vh.y, uh.y};   // s = 0
            uint32_t ah1[4] = {vh.z, uh.z, vh.w, uh.w};   // s = 1
            uint32_t al0[4] = {vl.x, ul.x, vl.y, ul.y};
            uint32_t al1[4] = {vl.z, ul.z, vl.w, ul.w};
#pragma unroll
            for (int in = 0; in < NF; in++) {
                uint32_t bh0[2] = {vbh[in].x, vbh[in].y};
                uint32_t bh1[2] = {vbh[in].z, vbh[in].w};
                uint32_t bl0[2] = {vbl[in].x, vbl[in].y};
                uint32_t bl1[2] = {vbl[in].z, vbl[in].w};
                mma_bf16(acc[im][in], ah0, bh0);
                mma_bf16(acc[im][in], ah0, bl0);
                mma_bf16(acc[im][in], al0, bh0);
                mma_bf16(acc[im][in], ah1, bh1);
                mma_bf16(acc[im][in], ah1, bl1);
                mma_bf16(acc[im][in], al1, bh1);
            }
        }
        __syncthreads();
    }

#pragma unroll
    for (int im = 0; im < 4; im++) {
        int r0 = bm + wm0 + im * 16 + gid;
#pragma unroll
        for (int in = 0; in < NF; in++) {
            int cc = wn0 + in * 8 + 2 * tg;
            float bx = bias[cc], by = bias[cc + 1];
            if (r0 < M) {
                float2 v = make_float2(acc[im][in][0] + bx, acc[im][in][1] + by);
                if (ACT) { v.x = elu1(v.x); v.y = elu1(v.y); }
                *(float2*)(C + (size_t)r0 * ldc + cc) = v;
            }
            if (r0 + 8 < M) {
                float2 v = make_float2(acc[im][in][2] + bx, acc[im][in][3] + by);
                if (ACT) { v.x = elu1(v.x); v.y = elu1(v.y); }
                *(float2*)(C + (size_t)(r0 + 8) * ldc + cc) = v;
            }
        }
    }
}

// --------- layer 1 edge phase, CSR, warp per node; writes h1 as permuted bf16 hi/lo ---------
__global__ void k_edge1_csr(const float* __restrict__ att,
                            const float* __restrict__ bias, int N) {
    int gt = blockIdx.x * blockDim.x + threadIdx.x;
    int lane = gt & 31, w = gt >> 5;
    if (w >= N) return;

    float4 attr = *(const float4*)(att + lane * 4);
    float4 b = *(const float4*)(g_xr1 + (size_t)w * 128 + lane * 4);

    int beg = g_rowptr[w], end = g_rowptr[w + 1];
    float4 acc = make_float4(0.f, 0.f, 0.f, 0.f);
    float den = 0.f;

    int s = g_esrc[beg];
    float4 a = *(const float4*)(g_xl1 + (size_t)s * 128 + lane * 4);
    for (int p = beg; p < end; p++) {
        float4 ac = a;
        if (p + 1 < end) {
            s = g_esrc[p + 1];
            a = *(const float4*)(g_xl1 + (size_t)s * 128 + lane * 4);
        }
        float z0 = ac.x + b.x; z0 = z0 > 0.f ? z0 : 0.2f * z0;
        float z1 = ac.y + b.y; z1 = z1 > 0.f ? z1 : 0.2f * z1;
        float z2 = ac.z + b.z; z2 = z2 > 0.f ? z2 : 0.2f * z2;
        float z3 = ac.w + b.w; z3 = z3 > 0.f ? z3 : 0.2f * z3;
        float part = attr.x * z0 + attr.y * z1 + attr.z * z2 + attr.w * z3;
        part += __shfl_xor_sync(0xffffffffu, part, 1);
        part += __shfl_xor_sync(0xffffffffu, part, 2);
        float ex = __expf(part);
        den += ex;
        acc.x += ac.x * ex; acc.y += ac.y * ex;
        acc.z += ac.z * ex; acc.w += ac.w * ex;
    }

    float inv = 1.f / den;
    int c = lane * 4;
    float o[4];
    o[0] = elu1(acc.x * inv + bias[c + 0]);
    o[1] = elu1(acc.y * inv + bias[c + 1]);
    o[2] = elu1(acc.z * inv + bias[c + 2]);
    o[3] = elu1(acc.w * inv + bias[c + 3]);
    __nv_bfloat16 h[4], l[4];
#pragma unroll
    for (int q = 0; q < 4; q++) split_bf(o[q], h[q], l[q]);
    size_t base = (size_t)w * 128;
    int p0 = permk(c), p1 = permk(c + 2);
    *(uint32_t*)(g_h1h + base + p0) = *(uint32_t*)&h[0];
    *(uint32_t*)(g_h1h + base + p1) = *(uint32_t*)&h[2];
    *(uint32_t*)(g_h1l + base + p0) = *(uint32_t*)&l[0];
    *(uint32_t*)(g_h1l + base + p1) = *(uint32_t*)&l[2];
}

// --------- layer 2 edge pass, CSR, warp per node; writes h2 as permuted bf16 hi/lo ---------
__global__ void k_edge2_csr(const float* __restrict__ att,
                            const float* __restrict__ bias, int N) {
    int gt = blockIdx.x * blockDim.x + threadIdx.x;
    int lane = gt & 31, w = gt >> 5;
    if (w >= N) return;

    float2 attr = *(const float2*)(att + lane * 2);
    float2 b = *(const float2*)(g_xr2 + (size_t)w * 64 + lane * 2);

    int beg = g_rowptr[w], end = g_rowptr[w + 1];
    float2 acc = make_float2(0.f, 0.f);
    float den = 0.f;

    int s = g_esrc[beg];
    float2 a = *(const float2*)(g_xl2 + (size_t)s * 64 + lane * 2);
    for (int p = beg; p < end; p++) {
        float2 ac = a;
        if (p + 1 < end) {
            s = g_esrc[p + 1];
            a = *(const float2*)(g_xl2 + (size_t)s * 64 + lane * 2);
        }
        float z0 = ac.x + b.x; z0 = z0 > 0.f ? z0 : 0.2f * z0;
        float z1 = ac.y + b.y; z1 = z1 > 0.f ? z1 : 0.2f * z1;
        float part = attr.x * z0 + attr.y * z1;
        part += __shfl_xor_sync(0xffffffffu, part, 1);
        part += __shfl_xor_sync(0xffffffffu, part, 2);
        part += __shfl_xor_sync(0xffffffffu, part, 4);
        part += __shfl_xor_sync(0xffffffffu, part, 8);
        part += __shfl_xor_sync(0xffffffffu, part, 16);
        float ex = __expf(part);
        den += ex;
        acc.x += ac.x * ex; acc.y += ac.y * ex;
    }

    float inv = 1.f / den;
    int c = lane * 2;
    float o0 = elu1(acc.x * inv + bias[c + 0]);
    float o1 = elu1(acc.y * inv + bias[c + 1]);
    __nv_bfloat16 h[2], l[2];
    split_bf(o0, h[0], l[0]);
    split_bf(o1, h[1], l[1]);
    size_t base = (size_t)w * 64;
    int p0 = permk(c);
    *(uint32_t*)(g_h2h + base + p0) = *(uint32_t*)&h[0];
    *(uint32_t*)(g_h2l + base + p0) = *(uint32_t*)&l[0];
}

// ------------------------- launch -------------------------
static inline int cdiv(int a, int b) { return (a + b - 1) / b; }

extern "C" void kernel_launch(void* const* d_in, const int* in_sizes, int n_in,
                              void* d_out, int out_size) {
    const float* x     = (const float*)d_in[0];
    const int*   ei    = (const int*)d_in[1];
    const float* Wl1   = (const float*)d_in[2];
    const float* bl1   = (const float*)d_in[3];
    const float* Wr1   = (const float*)d_in[4];
    const float* br1   = (const float*)d_in[5];
    const float* att1  = (const float*)d_in[6];
    const float* bias1 = (const float*)d_in[7];
    const float* Wl2   = (const float*)d_in[8];
    const float* bl2   = (const float*)d_in[9];
    const float* Wr2   = (const float*)d_in[10];
    const float* br2   = (const float*)d_in[11];
    const float* att2  = (const float*)d_in[12];
    const float* bias2 = (const float*)d_in[13];
    const float* Wlin  = (const float*)d_in[14];
    const float* blin  = (const float*)d_in[15];

    int N = in_sizes[0] / 128;
    int E = in_sizes[1] / 2;
    int Etot = E + N;
    int NB = cdiv(N, 256);

    // precompute bf16 hi/lo (permuted) inputs and transposed weights
    k_cvtA<<<cdiv(N * 128, 1024), 256>>>(x, N * 128);
    k_cvtW<<<224, 256>>>(Wl1, Wr1, Wl2, Wr2, Wlin);

    k_initdeg<<<NB, 256>>>(N);

    // layer-1 dual GEMM (profiled slot #4)
    dim3 g1(cdiv(N, 128), 2);
    k_gemm_bf<128, 128, 0, 0, 1, 1><<<g1, 256>>>(bl1, br1, nullptr, N);

    // CSR build (rest)
    k_hist<<<cdiv(E, 256), 256>>>(ei, E);
    k_scanblk<<<NB, 256>>>(N);
    k_scantop<<<1, 256>>>(NB);
    k_finalize<<<NB, 256>>>(N, Etot);
    k_scatter<<<cdiv(E, 256), 256>>>(ei, E);

    // layer 1 edge phase
    k_edge1_csr<<<cdiv(N * 32, 256), 256>>>(att1, bias1, N);

    // layer 2
    dim3 g2(cdiv(N, 128), 2);
    k_gemm_bf<128, 64, 0, 1, 2, 2><<<g2, 256>>>(bl2, br2, nullptr, N);
    k_edge2_csr<<<cdiv(N * 32, 256), 256>>>(att2, bias2, N);

    // final linear + ELU -> d_out [N,128]
    dim3 g3(cdiv(N, 128), 1);
    k_gemm_bf<64, 128, 1, 2, 3, 0><<<g3, 256>>>(blin, blin, (float*)d_out, N);
}

// round 13
// speedup vs baseline: 1.3547x; 1.0364x over previous
#include <cuda_runtime.h>
#include <cuda_bf16.h>
#include <cstdint>

#define NMAX    50048
#define EMAX    800000
#define ETOTMAX (NMAX + EMAX)
#define NBLKMAX 256

// ------------------------- scratch (device globals) -------------------------
__device__ __align__(16) float g_xl1[NMAX * 128];
__device__ __align__(16) float g_xr1[NMAX * 128];
__device__ __align__(16) float g_xl2[NMAX * 64];
__device__ __align__(16) float g_xr2[NMAX * 64];
// bf16 hi/lo GEMM inputs, PERMUTED k-order within each row (see permk)
__device__ __align__(16) __nv_bfloat16 g_xh [NMAX * 128];
__device__ __align__(16) __nv_bfloat16 g_xlo[NMAX * 128];
__device__ __align__(16) __nv_bfloat16 g_h1h[NMAX * 128];
__device__ __align__(16) __nv_bfloat16 g_h1l[NMAX * 128];
__device__ __align__(16) __nv_bfloat16 g_h2h[NMAX * 64];
__device__ __align__(16) __nv_bfloat16 g_h2l[NMAX * 64];
// weights, transposed to [col][k] with permuted k, bf16 hi/lo
__device__ __align__(16) __nv_bfloat16 g_w1h[2 * 128 * 128];
__device__ __align__(16) __nv_bfloat16 g_w1l[2 * 128 * 128];
__device__ __align__(16) __nv_bfloat16 g_w2h[2 * 64 * 128];
__device__ __align__(16) __nv_bfloat16 g_w2l[2 * 64 * 128];
__device__ __align__(16) __nv_bfloat16 g_w3h[128 * 64];
__device__ __align__(16) __nv_bfloat16 g_w3l[128 * 64];
// CSR   (g_deg is ZERO at module load; k_finalize re-zeros it each run)
__device__ __align__(16) int g_deg[NMAX];
__device__ __align__(16) int g_pre[NMAX];
__device__ __align__(16) int g_bsum[NBLKMAX];
__device__ __align__(16) int g_rowptr[NMAX + 1];
__device__ __align__(16) int g_cursor[NMAX];
__device__ __align__(16) int g_esrc[ETOTMAX];

// ------------------------- helpers -------------------------
__device__ __forceinline__ float elu1(float v) { return v > 0.f ? v : expm1f(v); }

__device__ __forceinline__ void split_bf(float v, __nv_bfloat16& h, __nv_bfloat16& l) {
    h = __float2bfloat16_rn(v);
    l = __float2bfloat16_rn(v - __bfloat162float(h));
}

// permuted element index within a row: per 32-elem chunk, word j (2 elems) goes to
// slot pos(j) = (j%4)*4 + j/4, so a fragment thread's 4 words are one uint4.
__device__ __forceinline__ int permk(int k) {
    int chunk = k >> 5;
    int j = (k & 31) >> 1;
    int lo = k & 1;
    int pos = (j & 3) * 4 + (j >> 2);
    return chunk * 32 + pos * 2 + lo;
}

__device__ __forceinline__ void mma_bf16(float* c, const uint32_t* a, const uint32_t* b) {
    asm volatile(
        "mma.sync.aligned.m16n8k16.row.col.f32.bf16.bf16.f32 "
        "{%0,%1,%2,%3}, {%4,%5,%6,%7}, {%8,%9}, {%0,%1,%2,%3};\n"
        : "+f"(c[0]), "+f"(c[1]), "+f"(c[2]), "+f"(c[3])
        : "r"(a[0]), "r"(a[1]), "r"(a[2]), "r"(a[3]), "r"(b[0]), "r"(b[1]));
}

__device__ __forceinline__ uint32_t s2u(const void* p) {
    return (uint32_t)__cvta_generic_to_shared(p);
}
#define CP16(dst, src) \
    asm volatile("cp.async.cg.shared.global [%0], [%1], 16;\n" :: "r"(dst), "l"(src))
#define CP_COMMIT() asm volatile("cp.async.commit_group;\n" ::: "memory")
#define CP_WAIT0()  asm volatile("cp.async.wait_group 0;\n" ::: "memory")
#define CP_WAIT1()  asm volatile("cp.async.wait_group 1;\n" ::: "memory")

// --------- merged conversion kernel: blocks [0, GW) do weights, rest do x ---------
__global__ void k_cvt(const float* __restrict__ x, int n,
                      const float* __restrict__ Wl1, const float* __restrict__ Wr1,
                      const float* __restrict__ Wl2, const float* __restrict__ Wr2,
                      const float* __restrict__ Wlin, int GW) {
    if ((int)blockIdx.x < GW) {
        int i = blockIdx.x * blockDim.x + threadIdx.x;   // 57344 total
        if (i < 32768) {                                  // L1: m, col(128), k(128)
            int m = i >> 14, r = i & 16383, c = r >> 7, k = r & 127;
            const float* W = m ? Wr1 : Wl1;
            int o = (m << 14) + (c << 7) + permk(k);
            split_bf(W[k * 128 + c], g_w1h[o], g_w1l[o]);
        } else if (i < 49152) {                           // L2: m, col(64), k(128)
            int j = i - 32768;
            int m = j >> 13, r = j & 8191, c = r >> 7, k = r & 127;
            const float* W = m ? Wr2 : Wl2;
            int o = (m << 13) + (c << 7) + permk(k);
            split_bf(W[k * 64 + c], g_w2h[o], g_w2l[o]);
        } else if (i < 57344) {                           // lin: col(128), k(64)
            int j = i - 49152;
            int c = j >> 6, k = j & 63;
            int o = (c << 6) + permk(k);
            split_bf(Wlin[k * 128 + c], g_w3h[o], g_w3l[o]);
        }
    } else {
        int i = ((blockIdx.x - GW) * blockDim.x + threadIdx.x) * 4;
        if (i < n) {
            float4 v = *(const float4*)(x + i);
            __nv_bfloat16 h[4], l[4];
            split_bf(v.x, h[0], l[0]); split_bf(v.y, h[1], l[1]);
            split_bf(v.z, h[2], l[2]); split_bf(v.w, h[3], l[3]);
            int base = i & ~127;
            int p0 = base + permk(i & 127);
            int p1 = base + permk((i & 127) + 2);
            *(uint32_t*)(g_xh  + p0) = *(uint32_t*)&h[0];
            *(uint32_t*)(g_xh  + p1) = *(uint32_t*)&h[2];
            *(uint32_t*)(g_xlo + p0) = *(uint32_t*)&l[0];
            *(uint32_t*)(g_xlo + p1) = *(uint32_t*)&l[2];
        }
    }
}

// ------------------------- CSR build -------------------------
__global__ void k_hist(const int* __restrict__ ei, int E) {
    int i = blockIdx.x * blockDim.x + threadIdx.x;
    if (i < E) atomicAdd(&g_deg[ei[E + i]], 1);
}
// block-level scan of (deg+1); deg itself stays un-reset until k_finalize
__global__ void k_scanblk(int N) {
    __shared__ int sh[256];
    int i = blockIdx.x * 256 + threadIdx.x;
    int v = (i < N) ? (g_deg[i] + 1) : 0;      // +1 = self-loop
    sh[threadIdx.x] = v;
    __syncthreads();
    for (int off = 1; off < 256; off <<= 1) {
        int t = (threadIdx.x >= off) ? sh[threadIdx.x - off] : 0;
        __syncthreads();
        sh[threadIdx.x] += t;
        __syncthreads();
    }
    if (i < N) g_pre[i] = sh[threadIdx.x] - v;   // exclusive
    if (threadIdx.x == 255) g_bsum[blockIdx.x] = sh[255];
}
// merged top-scan + finalize: every block redundantly scans g_bsum in smem
__global__ void k_finalize(int N, int Etot, int NB) {
    __shared__ int sh[256];
    __shared__ int exc[256];
    int t = threadIdx.x;
    int v = (t < NB) ? g_bsum[t] : 0;
    sh[t] = v;
    __syncthreads();
    for (int off = 1; off < 256; off <<= 1) {
        int u = (t >= off) ? sh[t - off] : 0;
        __syncthreads();
        sh[t] += u;
        __syncthreads();
    }
    exc[t] = sh[t] - v;
    __syncthreads();
    int i = blockIdx.x * 256 + t;
    if (i < N) {
        int rp = g_pre[i] + exc[i >> 8];
        g_rowptr[i] = rp;
        g_cursor[i] = rp + 1;
        g_esrc[rp] = i;                   // self-loop occupies first slot
        g_deg[i] = 0;                     // reset for next graph replay
        if (i == 0) g_rowptr[N] = Etot;
    }
}
__global__ void k_scatter(const int* __restrict__ ei, int E) {
    int i = blockIdx.x * blockDim.x + threadIdx.x;
    if (i < E) {
        int d = ei[E + i];
        int slot = atomicAdd(&g_cursor[d], 1);
        g_esrc[slot] = ei[i];
    }
}

// ----- bf16x3-split tensor GEMM, permuted-k inputs, 3-stage cp.async pipeline -----
// C[M,BN] = A[M,K] @ W[K,BN] + bias.  BM=128, BK=32, 256 thr = 8 warps (2m x 4n).
// ONE __syncthreads per chunk: fill targets buf c+2, compute reads buf c.
// SRC: 0 = g_xh/g_xlo (K=128), 1 = g_h1h/g_h1l (K=128), 2 = g_h2h/g_h2l (K=64).
// WSEL: 1 = g_w1 (+y*16384), 2 = g_w2 (+y*8192), 3 = g_w3.
// DSTSEL: 0 = Carg (ldc=BN), 1 = y-sel (xl1,xr1) ldc=128, 2 = y-sel (xl2,xr2) ldc=64.
template <int K, int BN, int ACT, int SRC, int WSEL, int DSTSEL>
__global__ __launch_bounds__(256, 2) void k_gemm_bf(const float* __restrict__ b0,
                                                    const float* __restrict__ b1,
                                                    float* __restrict__ Carg, int M) {
    const int NF = BN / 32;
    const int KU4 = K / 8;                    // uint4 per global row
    const int NC = K / 32;                    // k-chunks

    const __nv_bfloat16* Agh = (SRC == 0) ? g_xh : (SRC == 1 ? g_h1h : g_h2h);
    const __nv_bfloat16* Agl = (SRC == 0) ? g_xlo : (SRC == 1 ? g_h1l : g_h2l);
    const __nv_bfloat16* Bgh = (WSEL == 1) ? g_w1h + blockIdx.y * 16384
                              : (WSEL == 2) ? g_w2h + blockIdx.y * 8192 : g_w3h;
    const __nv_bfloat16* Bgl = (WSEL == 1) ? g_w1l + blockIdx.y * 16384
                              : (WSEL == 2) ? g_w2l + blockIdx.y * 8192 : g_w3l;
    const float* bias = (blockIdx.y == 0) ? b0 : b1;
    float* C;
    int ldc;
    if (DSTSEL == 0)      { C = Carg; ldc = BN; }
    else if (DSTSEL == 1) { C = (blockIdx.y == 0) ? g_xl1 : g_xr1; ldc = 128; }
    else                  { C = (blockIdx.y == 0) ? g_xl2 : g_xr2; ldc = 64; }

    // 3-stage buffers; rows of exactly 64B -> conflict-free LDS.128 frags
    __shared__ __nv_bfloat16 Ah[3][128][32];
    __shared__ __nv_bfloat16 Al[3][128][32];
    __shared__ __nv_bfloat16 Bh[3][BN][32];
    __shared__ __nv_bfloat16 Bl[3][BN][32];

    int tid  = threadIdx.x;
    int lane = tid & 31;
    int ww   = tid >> 5;
    int bm   = blockIdx.x * 128;
    int wm0  = (ww & 1) * 64;
    int wn0  = (ww >> 1) * (BN / 4);
    int tg   = lane & 3;
    int gid  = lane >> 2;

    // per-thread fill coordinates (chunk-invariant)
    int fa_row = tid >> 1, fa_q = (tid & 1) * 2;
    int fa_arow = bm + fa_row; if (fa_arow >= M) fa_arow = M - 1;
    const uint4* fa_ph = (const uint4*)Agh + (size_t)fa_arow * KU4;
    const uint4* fa_pl = (const uint4*)Agl + (size_t)fa_arow * KU4;

    float acc[4][NF][4] = {};

    auto fill = [&](int buf, int c) {
        int ck4 = c * 4;
        CP16(s2u(&Ah[buf][fa_row][fa_q * 8]),       fa_ph + ck4 + fa_q);
        CP16(s2u(&Ah[buf][fa_row][(fa_q + 1) * 8]), fa_ph + ck4 + fa_q + 1);
        CP16(s2u(&Al[buf][fa_row][fa_q * 8]),       fa_pl + ck4 + fa_q);
        CP16(s2u(&Al[buf][fa_row][(fa_q + 1) * 8]), fa_pl + ck4 + fa_q + 1);
#pragma unroll
        for (int q = tid; q < BN * 4; q += 256) {
            int col = q >> 2, part = q & 3;
            CP16(s2u(&Bh[buf][col][part * 8]),
                 (const uint4*)Bgh + (size_t)col * KU4 + ck4 + part);
            CP16(s2u(&Bl[buf][col][part * 8]),
                 (const uint4*)Bgl + (size_t)col * KU4 + ck4 + part);
        }
    };

    fill(0, 0);
    CP_COMMIT();
    if (NC > 1) { fill(1, 1); CP_COMMIT(); }

#pragma unroll
    for (int c = 0; c < NC; c++) {
        int buf = c % 3;
        if (c + 1 < NC) CP_WAIT1(); else CP_WAIT0();
        __syncthreads();                       // buf c ready; compute(c-1) done everywhere
        if (c + 2 < NC) { fill((c + 2) % 3, c + 2); CP_COMMIT(); }

        // B fragments for whole k-chunk (both k16 steps): 2*NF LDS.128
        uint4 vbh[NF], vbl[NF];
#pragma unroll
        for (int in = 0; in < NF; in++) {
            int nc = wn0 + in * 8 + gid;
            vbh[in] = *(const uint4*)&Bh[buf][nc][tg * 8];
            vbl[in] = *(const uint4*)&Bl[buf][nc][tg * 8];
        }

#pragma unroll
        for (int im = 0; im < 4; im++) {
            int mr = wm0 + im * 16 + gid;
            uint4 vh = *(const uint4*)&Ah[buf][mr][tg * 8];
            uint4 uh = *(const uint4*)&Ah[buf][mr + 8][tg * 8];
            uint4 vl = *(const uint4*)&Al[buf][mr][tg * 8];
            uint4 ul = *(const uint4*)&Al[buf][mr + 8][tg * 8];
            uint32_t ah0[4] = {vh.x, uh.x, vh.y, uh.y};   // s = 0
            uint32_t ah1[4] = {vh.z, uh.z, vh.w, uh.w};   // s = 1
            uint32_t al0[4] = {vl.x, ul.x, vl.y, ul.y};
            uint32_t al1[4] = {vl.z, ul.z, vl.w, ul.w};
#pragma unroll
            for (int in = 0; in < NF; in++) {
                uint32_t bh0[2] = {vbh[in].x, vbh[in].y};
                uint32_t bh1[2] = {vbh[in].z, vbh[in].w};
                uint32_t bl0[2] = {vbl[in].x, vbl[in].y};
                uint32_t bl1[2] = {vbl[in].z, vbl[in].w};
                mma_bf16(acc[im][in], ah0, bh0);
                mma_bf16(acc[im][in], ah0, bl0);
                mma_bf16(acc[im][in], al0, bh0);
                mma_bf16(acc[im][in], ah1, bh1);
                mma_bf16(acc[im][in], ah1, bl1);
                mma_bf16(acc[im][in], al1, bh1);
            }
        }
    }

#pragma unroll
    for (int im = 0; im < 4; im++) {
        int r0 = bm + wm0 + im * 16 + gid;
#pragma unroll
        for (int in = 0; in < NF; in++) {
            int cc = wn0 + in * 8 + 2 * tg;
            float bx = bias[cc], by = bias[cc + 1];
            if (r0 < M) {
                float2 v = make_float2(acc[im][in][0] + bx, acc[im][in][1] + by);
                if (ACT) { v.x = elu1(v.x); v.y = elu1(v.y); }
                *(float2*)(C + (size_t)r0 * ldc + cc) = v;
            }
            if (r0 + 8 < M) {
                float2 v = make_float2(acc[im][in][2] + bx, acc[im][in][3] + by);
                if (ACT) { v.x = elu1(v.x); v.y = elu1(v.y); }
                *(float2*)(C + (size_t)(r0 + 8) * ldc + cc) = v;
            }
        }
    }
}

// --------- layer 1 edge phase, CSR, warp per node; writes h1 as permuted bf16 hi/lo ---------
__global__ void k_edge1_csr(const float* __restrict__ att,
                            const float* __restrict__ bias, int N) {
    int gt = blockIdx.x * blockDim.x + threadIdx.x;
    int lane = gt & 31, w = gt >> 5;
    if (w >= N) return;

    float4 attr = *(const float4*)(att + lane * 4);
    float4 b = *(const float4*)(g_xr1 + (size_t)w * 128 + lane * 4);

    int beg = g_rowptr[w], end = g_rowptr[w + 1];
    float4 acc = make_float4(0.f, 0.f, 0.f, 0.f);
    float den = 0.f;

    int s = g_esrc[beg];
    float4 a = *(const float4*)(g_xl1 + (size_t)s * 128 + lane * 4);
    for (int p = beg; p < end; p++) {
        float4 ac = a;
        if (p + 1 < end) {
            s = g_esrc[p + 1];
            a = *(const float4*)(g_xl1 + (size_t)s * 128 + lane * 4);
        }
        float z0 = ac.x + b.x; z0 = z0 > 0.f ? z0 : 0.2f * z0;
        float z1 = ac.y + b.y; z1 = z1 > 0.f ? z1 : 0.2f * z1;
        float z2 = ac.z + b.z; z2 = z2 > 0.f ? z2 : 0.2f * z2;
        float z3 = ac.w + b.w; z3 = z3 > 0.f ? z3 : 0.2f * z3;
        float part = attr.x * z0 + attr.y * z1 + attr.z * z2 + attr.w * z3;
        part += __shfl_xor_sync(0xffffffffu, part, 1);
        part += __shfl_xor_sync(0xffffffffu, part, 2);
        float ex = __expf(part);
        den += ex;
        acc.x += ac.x * ex; acc.y += ac.y * ex;
        acc.z += ac.z * ex; acc.w += ac.w * ex;
    }

    float inv = 1.f / den;
    int c = lane * 4;
    float o[4];
    o[0] = elu1(acc.x * inv + bias[c + 0]);
    o[1] = elu1(acc.y * inv + bias[c + 1]);
    o[2] = elu1(acc.z * inv + bias[c + 2]);
    o[3] = elu1(acc.w * inv + bias[c + 3]);
    __nv_bfloat16 h[4], l[4];
#pragma unroll
    for (int q = 0; q < 4; q++) split_bf(o[q], h[q], l[q]);
    size_t base = (size_t)w * 128;
    int p0 = permk(c), p1 = permk(c + 2);
    *(uint32_t*)(g_h1h + base + p0) = *(uint32_t*)&h[0];
    *(uint32_t*)(g_h1h + base + p1) = *(uint32_t*)&h[2];
    *(uint32_t*)(g_h1l + base + p0) = *(uint32_t*)&l[0];
    *(uint32_t*)(g_h1l + base + p1) = *(uint32_t*)&l[2];
}

// --------- layer 2 edge pass, CSR, warp per node; writes h2 as permuted bf16 hi/lo ---------
__global__ void k_edge2_csr(const float* __restrict__ att,
                            const float* __restrict__ bias, int N) {
    int gt = blockIdx.x * blockDim.x + threadIdx.x;
    int lane = gt & 31, w = gt >> 5;
    if (w >= N) return;

    float2 attr = *(const float2*)(att + lane * 2);
    float2 b = *(const float2*)(g_xr2 + (size_t)w * 64 + lane * 2);

    int beg = g_rowptr[w], end = g_rowptr[w + 1];
    float2 acc = make_float2(0.f, 0.f);
    float den = 0.f;

    int s = g_esrc[beg];
    float2 a = *(const float2*)(g_xl2 + (size_t)s * 64 + lane * 2);
    for (int p = beg; p < end; p++) {
        float2 ac = a;
        if (p + 1 < end) {
            s = g_esrc[p + 1];
            a = *(const float2*)(g_xl2 + (size_t)s * 64 + lane * 2);
        }
        float z0 = ac.x + b.x; z0 = z0 > 0.f ? z0 : 0.2f * z0;
        float z1 = ac.y + b.y; z1 = z1 > 0.f ? z1 : 0.2f * z1;
        float part = attr.x * z0 + attr.y * z1;
        part += __shfl_xor_sync(0xffffffffu, part, 1);
        part += __shfl_xor_sync(0xffffffffu, part, 2);
        part += __shfl_xor_sync(0xffffffffu, part, 4);
        part += __shfl_xor_sync(0xffffffffu, part, 8);
        part += __shfl_xor_sync(0xffffffffu, part, 16);
        float ex = __expf(part);
        den += ex;
        acc.x += ac.x * ex; acc.y += ac.y * ex;
    }

    float inv = 1.f / den;
    int c = lane * 2;
    float o0 = elu1(acc.x * inv + bias[c + 0]);
    float o1 = elu1(acc.y * inv + bias[c + 1]);
    __nv_bfloat16 h[2], l[2];
    split_bf(o0, h[0], l[0]);
    split_bf(o1, h[1], l[1]);
    size_t base = (size_t)w * 64;
    int p0 = permk(c);
    *(uint32_t*)(g_h2h + base + p0) = *(uint32_t*)&h[0];
    *(uint32_t*)(g_h2l + base + p0) = *(uint32_t*)&l[0];
}

// ------------------------- launch -------------------------
static inline int cdiv(int a, int b) { return (a + b - 1) / b; }

extern "C" void kernel_launch(void* const* d_in, const int* in_sizes, int n_in,
                              void* d_out, int out_size) {
    const float* x     = (const float*)d_in[0];
    const int*   ei    = (const int*)d_in[1];
    const float* Wl1   = (const float*)d_in[2];
    const float* bl1   = (const float*)d_in[3];
    const float* Wr1   = (const float*)d_in[4];
    const float* br1   = (const float*)d_in[5];
    const float* att1  = (const float*)d_in[6];
    const float* bias1 = (const float*)d_in[7];
    const float* Wl2   = (const float*)d_in[8];
    const float* bl2   = (const float*)d_in[9];
    const float* Wr2   = (const float*)d_in[10];
    const float* br2   = (const float*)d_in[11];
    const float* att2  = (const float*)d_in[12];
    const float* bias2 = (const float*)d_in[13];
    const float* Wlin  = (const float*)d_in[14];
    const float* blin  = (const float*)d_in[15];

    int N = in_sizes[0] / 128;
    int E = in_sizes[1] / 2;
    int Etot = E + N;
    int NB = cdiv(N, 256);
    int GW = 224;                              // weight-conversion blocks

    // #1: merged conversions (weights + x -> permuted bf16 hi/lo)
    k_cvt<<<GW + cdiv(N * 128, 1024), 256>>>(x, N * 128, Wl1, Wr1, Wl2, Wr2, Wlin, GW);
    // #2, #3: CSR histogram + block scan
    k_hist<<<cdiv(E, 256), 256>>>(ei, E);
    k_scanblk<<<NB, 256>>>(N);

    // #4 (profiled slot): layer-1 dual GEMM
    dim3 g1(cdiv(N, 128), 2);
    k_gemm_bf<128, 128, 0, 0, 1, 1><<<g1, 256>>>(bl1, br1, nullptr, N);

    // #5, #6: CSR finalize (top scan fused) + scatter
    k_finalize<<<NB, 256>>>(N, Etot, NB);
    k_scatter<<<cdiv(E, 256), 256>>>(ei, E);

    // layer 1 edge phase
    k_edge1_csr<<<cdiv(N * 32, 256), 256>>>(att1, bias1, N);

    // layer 2
    dim3 g2(cdiv(N, 128), 2);
    k_gemm_bf<128, 64, 0, 1, 2, 2><<<g2, 256>>>(bl2, br2, nullptr, N);
    k_edge2_csr<<<cdiv(N * 32, 256), 256>>>(att2, bias2, N);

    // final linear + ELU -> d_out [N,128]
    dim3 g3(cdiv(N, 128), 1);
    k_gemm_bf<64, 128, 1, 2, 3, 0><<<g3, 256>>>(blin, blin, (float*)d_out, N);
}

// round 14
// speedup vs baseline: 1.4112x; 1.0417x over previous
#include <cuda_runtime.h>
#include <cuda_bf16.h>
#include <cstdint>

#define NMAX    50048
#define EMAX    800000
#define ETOTMAX (NMAX + EMAX)
#define NBLKMAX 256

// ------------------------- scratch (device globals) -------------------------
__device__ __align__(16) float g_xl1[NMAX * 128];
__device__ __align__(16) float g_xr1[NMAX * 128];
__device__ __align__(16) float g_xl2[NMAX * 64];
__device__ __align__(16) float g_xr2[NMAX * 64];
// bf16 hi/lo GEMM inputs, PERMUTED k-order within each row (see permk)
__device__ __align__(16) __nv_bfloat16 g_xh [NMAX * 128];
__device__ __align__(16) __nv_bfloat16 g_xlo[NMAX * 128];
__device__ __align__(16) __nv_bfloat16 g_h1h[NMAX * 128];
__device__ __align__(16) __nv_bfloat16 g_h1l[NMAX * 128];
__device__ __align__(16) __nv_bfloat16 g_h2h[NMAX * 64];
__device__ __align__(16) __nv_bfloat16 g_h2l[NMAX * 64];
// weights, transposed to [col][k] with permuted k, bf16 hi/lo
__device__ __align__(16) __nv_bfloat16 g_w1h[2 * 128 * 128];
__device__ __align__(16) __nv_bfloat16 g_w1l[2 * 128 * 128];
__device__ __align__(16) __nv_bfloat16 g_w2h[2 * 64 * 128];
__device__ __align__(16) __nv_bfloat16 g_w2l[2 * 64 * 128];
__device__ __align__(16) __nv_bfloat16 g_w3h[128 * 64];
__device__ __align__(16) __nv_bfloat16 g_w3l[128 * 64];
// CSR   (g_deg is ZERO at module load; k_finalize re-zeros it each run)
__device__ __align__(16) int g_deg[NMAX];
__device__ __align__(16) int g_pre[NMAX];
__device__ __align__(16) int g_bsum[NBLKMAX];
__device__ __align__(16) int g_rowptr[NMAX + 1];
__device__ __align__(16) int g_cursor[NMAX];
__device__ __align__(16) int g_esrc[ETOTMAX];

// ------------------------- helpers -------------------------
__device__ __forceinline__ float elu1(float v) { return v > 0.f ? v : expm1f(v); }

__device__ __forceinline__ void split_bf(float v, __nv_bfloat16& h, __nv_bfloat16& l) {
    h = __float2bfloat16_rn(v);
    l = __float2bfloat16_rn(v - __bfloat162float(h));
}

// permuted element index within a row: per 32-elem chunk, word j (2 elems) goes to
// slot pos(j) = (j%4)*4 + j/4, so a fragment thread's 4 words are one uint4.
__device__ __forceinline__ int permk(int k) {
    int chunk = k >> 5;
    int j = (k & 31) >> 1;
    int lo = k & 1;
    int pos = (j & 3) * 4 + (j >> 2);
    return chunk * 32 + pos * 2 + lo;
}

__device__ __forceinline__ void mma_bf16(float* c, const uint32_t* a, const uint32_t* b) {
    asm volatile(
        "mma.sync.aligned.m16n8k16.row.col.f32.bf16.bf16.f32 "
        "{%0,%1,%2,%3}, {%4,%5,%6,%7}, {%8,%9}, {%0,%1,%2,%3};\n"
        : "+f"(c[0]), "+f"(c[1]), "+f"(c[2]), "+f"(c[3])
        : "r"(a[0]), "r"(a[1]), "r"(a[2]), "r"(a[3]), "r"(b[0]), "r"(b[1]));
}

__device__ __forceinline__ uint32_t s2u(const void* p) {
    return (uint32_t)__cvta_generic_to_shared(p);
}
#define CP16(dst, src) \
    asm volatile("cp.async.cg.shared.global [%0], [%1], 16;\n" :: "r"(dst), "l"(src))
#define CP_COMMIT() asm volatile("cp.async.commit_group;\n" ::: "memory")
#define CP_WAIT0()  asm volatile("cp.async.wait_group 0;\n" ::: "memory")
#define CP_WAIT1()  asm volatile("cp.async.wait_group 1;\n" ::: "memory")

// ------------- side stream + events for CSR fork/join (created at load) -------------
static cudaStream_t g_s2;
static cudaEvent_t  g_evFork, g_evCsr;
namespace {
struct _StreamInit {
    _StreamInit() {
        cudaStreamCreateWithFlags(&g_s2, cudaStreamNonBlocking);
        cudaEventCreateWithFlags(&g_evFork, cudaEventDisableTiming);
        cudaEventCreateWithFlags(&g_evCsr, cudaEventDisableTiming);
    }
};
_StreamInit _streamInit;
}

// --------- merged conversion kernel: blocks [0, GW) do weights, rest do x ---------
__global__ void k_cvt(const float* __restrict__ x, int n,
                      const float* __restrict__ Wl1, const float* __restrict__ Wr1,
                      const float* __restrict__ Wl2, const float* __restrict__ Wr2,
                      const float* __restrict__ Wlin, int GW) {
    if ((int)blockIdx.x < GW) {
        int i = blockIdx.x * blockDim.x + threadIdx.x;   // 57344 total
        if (i < 32768) {                                  // L1: m, col(128), k(128)
            int m = i >> 14, r = i & 16383, c = r >> 7, k = r & 127;
            const float* W = m ? Wr1 : Wl1;
            int o = (m << 14) + (c << 7) + permk(k);
            split_bf(W[k * 128 + c], g_w1h[o], g_w1l[o]);
        } else if (i < 49152) {                           // L2: m, col(64), k(128)
            int j = i - 32768;
            int m = j >> 13, r = j & 8191, c = r >> 7, k = r & 127;
            const float* W = m ? Wr2 : Wl2;
            int o = (m << 13) + (c << 7) + permk(k);
            split_bf(W[k * 64 + c], g_w2h[o], g_w2l[o]);
        } else if (i < 57344) {                           // lin: col(128), k(64)
            int j = i - 49152;
            int c = j >> 6, k = j & 63;
            int o = (c << 6) + permk(k);
            split_bf(Wlin[k * 128 + c], g_w3h[o], g_w3l[o]);
        }
    } else {
        int i = ((blockIdx.x - GW) * blockDim.x + threadIdx.x) * 4;
        if (i < n) {
            float4 v = *(const float4*)(x + i);
            __nv_bfloat16 h[4], l[4];
            split_bf(v.x, h[0], l[0]); split_bf(v.y, h[1], l[1]);
            split_bf(v.z, h[2], l[2]); split_bf(v.w, h[3], l[3]);
            int base = i & ~127;
            int p0 = base + permk(i & 127);
            int p1 = base + permk((i & 127) + 2);
            *(uint32_t*)(g_xh  + p0) = *(uint32_t*)&h[0];
            *(uint32_t*)(g_xh  + p1) = *(uint32_t*)&h[2];
            *(uint32_t*)(g_xlo + p0) = *(uint32_t*)&l[0];
            *(uint32_t*)(g_xlo + p1) = *(uint32_t*)&l[2];
        }
    }
}

// ------------------------- CSR build -------------------------
__global__ void k_hist(const int* __restrict__ ei, int E) {
    int i = blockIdx.x * blockDim.x + threadIdx.x;
    if (i < E) atomicAdd(&g_deg[ei[E + i]], 1);
}
// block-level scan of (deg+1); deg itself stays un-reset until k_finalize
__global__ void k_scanblk(int N) {
    __shared__ int sh[256];
    int i = blockIdx.x * 256 + threadIdx.x;
    int v = (i < N) ? (g_deg[i] + 1) : 0;      // +1 = self-loop
    sh[threadIdx.x] = v;
    __syncthreads();
    for (int off = 1; off < 256; off <<= 1) {
        int t = (threadIdx.x >= off) ? sh[threadIdx.x - off] : 0;
        __syncthreads();
        sh[threadIdx.x] += t;
        __syncthreads();
    }
    if (i < N) g_pre[i] = sh[threadIdx.x] - v;   // exclusive
    if (threadIdx.x == 255) g_bsum[blockIdx.x] = sh[255];
}
// merged top-scan + finalize: every block redundantly scans g_bsum in smem
__global__ void k_finalize(int N, int Etot, int NB) {
    __shared__ int sh[256];
    __shared__ int exc[256];
    int t = threadIdx.x;
    int v = (t < NB) ? g_bsum[t] : 0;
    sh[t] = v;
    __syncthreads();
    for (int off = 1; off < 256; off <<= 1) {
        int u = (t >= off) ? sh[t - off] : 0;
        __syncthreads();
        sh[t] += u;
        __syncthreads();
    }
    exc[t] = sh[t] - v;
    __syncthreads();
    int i = blockIdx.x * 256 + t;
    if (i < N) {
        int rp = g_pre[i] + exc[i >> 8];
        g_rowptr[i] = rp;
        g_cursor[i] = rp + 1;
        g_esrc[rp] = i;                   // self-loop occupies first slot
        g_deg[i] = 0;                     // reset for next graph replay
        if (i == 0) g_rowptr[N] = Etot;
    }
}
__global__ void k_scatter(const int* __restrict__ ei, int E) {
    int i = blockIdx.x * blockDim.x + threadIdx.x;
    if (i < E) {
        int d = ei[E + i];
        int slot = atomicAdd(&g_cursor[d], 1);
        g_esrc[slot] = ei[i];
    }
}

// ----- bf16x3-split tensor GEMM, permuted-k inputs, 3-stage cp.async pipeline -----
// C[M,BN] = A[M,K] @ W[K,BN] + bias.  BM=128, BK=32, 256 thr = 8 warps (2m x 4n).
// ONE __syncthreads per chunk: fill targets buf c+2, compute reads buf c.
// SRC: 0 = g_xh/g_xlo (K=128), 1 = g_h1h/g_h1l (K=128), 2 = g_h2h/g_h2l (K=64).
// WSEL: 1 = g_w1 (+y*16384), 2 = g_w2 (+y*8192), 3 = g_w3.
// DSTSEL: 0 = Carg (ldc=BN), 1 = y-sel (xl1,xr1) ldc=128, 2 = y-sel (xl2,xr2) ldc=64.
template <int K, int BN, int ACT, int SRC, int WSEL, int DSTSEL>
__global__ __launch_bounds__(256, 2) void k_gemm_bf(const float* __restrict__ b0,
                                                    const float* __restrict__ b1,
                                                    float* __restrict__ Carg, int M) {
    const int NF = BN / 32;
    const int KU4 = K / 8;                    // uint4 per global row
    const int NC = K / 32;                    // k-chunks

    const __nv_bfloat16* Agh = (SRC == 0) ? g_xh : (SRC == 1 ? g_h1h : g_h2h);
    const __nv_bfloat16* Agl = (SRC == 0) ? g_xlo : (SRC == 1 ? g_h1l : g_h2l);
    const __nv_bfloat16* Bgh = (WSEL == 1) ? g_w1h + blockIdx.y * 16384
                              : (WSEL == 2) ? g_w2h + blockIdx.y * 8192 : g_w3h;
    const __nv_bfloat16* Bgl = (WSEL == 1) ? g_w1l + blockIdx.y * 16384
                              : (WSEL == 2) ? g_w2l + blockIdx.y * 8192 : g_w3l;
    const float* bias = (blockIdx.y == 0) ? b0 : b1;
    float* C;
    int ldc;
    if (DSTSEL == 0)      { C = Carg; ldc = BN; }
    else if (DSTSEL == 1) { C = (blockIdx.y == 0) ? g_xl1 : g_xr1; ldc = 128; }
    else                  { C = (blockIdx.y == 0) ? g_xl2 : g_xr2; ldc = 64; }

    // 3-stage buffers; rows of exactly 64B -> conflict-free LDS.128 frags
    __shared__ __nv_bfloat16 Ah[3][128][32];
    __shared__ __nv_bfloat16 Al[3][128][32];
    __shared__ __nv_bfloat16 Bh[3][BN][32];
    __shared__ __nv_bfloat16 Bl[3][BN][32];

    int tid  = threadIdx.x;
    int lane = tid & 31;
    int ww   = tid >> 5;
    int bm   = blockIdx.x * 128;
    int wm0  = (ww & 1) * 64;
    int wn0  = (ww >> 1) * (BN / 4);
    int tg   = lane & 3;
    int gid  = lane >> 2;

    // per-thread fill coordinates (chunk-invariant)
    int fa_row = tid >> 1, fa_q = (tid & 1) * 2;
    int fa_arow = bm + fa_row; if (fa_arow >= M) fa_arow = M - 1;
    const uint4* fa_ph = (const uint4*)Agh + (size_t)fa_arow * KU4;
    const uint4* fa_pl = (const uint4*)Agl + (size_t)fa_arow * KU4;

    float acc[4][NF][4] = {};

    auto fill = [&](int buf, int c) {
        int ck4 = c * 4;
        CP16(s2u(&Ah[buf][fa_row][fa_q * 8]),       fa_ph + ck4 + fa_q);
        CP16(s2u(&Ah[buf][fa_row][(fa_q + 1) * 8]), fa_ph + ck4 + fa_q + 1);
        CP16(s2u(&Al[buf][fa_row][fa_q * 8]),       fa_pl + ck4 + fa_q);
        CP16(s2u(&Al[buf][fa_row][(fa_q + 1) * 8]), fa_pl + ck4 + fa_q + 1);
#pragma unroll
        for (int q = tid; q < BN * 4; q += 256) {
            int col = q >> 2, part = q & 3;
            CP16(s2u(&Bh[buf][col][part * 8]),
                 (const uint4*)Bgh + (size_t)col * KU4 + ck4 + part);
            CP16(s2u(&Bl[buf][col][part * 8]),
                 (const uint4*)Bgl + (size_t)col * KU4 + ck4 + part);
        }
    };

    fill(0, 0);
    CP_COMMIT();
    if (NC > 1) { fill(1, 1); CP_COMMIT(); }

#pragma unroll
    for (int c = 0; c < NC; c++) {
        int buf = c % 3;
        if (c + 1 < NC) CP_WAIT1(); else CP_WAIT0();
        __syncthreads();                       // buf c ready; compute(c-1) done everywhere
        if (c + 2 < NC) { fill((c + 2) % 3, c + 2); CP_COMMIT(); }

        // B fragments for whole k-chunk (both k16 steps): 2*NF LDS.128
        uint4 vbh[NF], vbl[NF];
#pragma unroll
        for (int in = 0; in < NF; in++) {
            int nc = wn0 + in * 8 + gid;
            vbh[in] = *(const uint4*)&Bh[buf][nc][tg * 8];
            vbl[in] = *(const uint4*)&Bl[buf][nc][tg * 8];
        }

#pragma unroll
        for (int im = 0; im < 4; im++) {
            int mr = wm0 + im * 16 + gid;
            uint4 vh = *(const uint4*)&Ah[buf][mr][tg * 8];
            uint4 uh = *(const uint4*)&Ah[buf][mr + 8][tg * 8];
            uint4 vl = *(const uint4*)&Al[buf][mr][tg * 8];
            uint4 ul = *(const uint4*)&Al[buf][mr + 8][tg * 8];
            uint32_t ah0[4] = {vh.x, uh.x, vh.y, uh.y};   // s = 0
            uint32_t ah1[4] = {vh.z, uh.z, vh.w, uh.w};   // s = 1
            uint32_t al0[4] = {vl.x, ul.x, vl.y, ul.y};
            uint32_t al1[4] = {vl.z, ul.z, vl.w, ul.w};
#pragma unroll
            for (int in = 0; in < NF; in++) {
                uint32_t bh0[2] = {vbh[in].x, vbh[in].y};
                uint32_t bh1[2] = {vbh[in].z, vbh[in].w};
                uint32_t bl0[2] = {vbl[in].x, vbl[in].y};
                uint32_t bl1[2] = {vbl[in].z, vbl[in].w};
                mma_bf16(acc[im][in], ah0, bh0);
                mma_bf16(acc[im][in], ah0, bl0);
                mma_bf16(acc[im][in], al0, bh0);
                mma_bf16(acc[im][in], ah1, bh1);
                mma_bf16(acc[im][in], ah1, bl1);
                mma_bf16(acc[im][in], al1, bh1);
            }
        }
    }

#pragma unroll
    for (int im = 0; im < 4; im++) {
        int r0 = bm + wm0 + im * 16 + gid;
#pragma unroll
        for (int in = 0; in < NF; in++) {
            int cc = wn0 + in * 8 + 2 * tg;
            float bx = bias[cc], by = bias[cc + 1];
            if (r0 < M) {
                float2 v = make_float2(acc[im][in][0] + bx, acc[im][in][1] + by);
                if (ACT) { v.x = elu1(v.x); v.y = elu1(v.y); }
                *(float2*)(C + (size_t)r0 * ldc + cc) = v;
            }
            if (r0 + 8 < M) {
                float2 v = make_float2(acc[im][in][2] + bx, acc[im][in][3] + by);
                if (ACT) { v.x = elu1(v.x); v.y = elu1(v.y); }
                *(float2*)(C + (size_t)(r0 + 8) * ldc + cc) = v;
            }
        }
    }
}

// --------- layer 1 edge phase, CSR, warp per node; writes h1 as permuted bf16 hi/lo ---------
__global__ void k_edge1_csr(const float* __restrict__ att,
                            const float* __restrict__ bias, int N) {
    int gt = blockIdx.x * blockDim.x + threadIdx.x;
    int lane = gt & 31, w = gt >> 5;
    if (w >= N) return;

    float4 attr = *(const float4*)(att + lane * 4);
    float4 b = *(const float4*)(g_xr1 + (size_t)w * 128 + lane * 4);

    int beg = g_rowptr[w], end = g_rowptr[w + 1];
    float4 acc = make_float4(0.f, 0.f, 0.f, 0.f);
    float den = 0.f;

    int s = g_esrc[beg];
    float4 a = *(const float4*)(g_xl1 + (size_t)s * 128 + lane * 4);
    for (int p = beg; p < end; p++) {
        float4 ac = a;
        if (p + 1 < end) {
            s = g_esrc[p + 1];
            a = *(const float4*)(g_xl1 + (size_t)s * 128 + lane * 4);
        }
        float z0 = ac.x + b.x; z0 = z0 > 0.f ? z0 : 0.2f * z0;
        float z1 = ac.y + b.y; z1 = z1 > 0.f ? z1 : 0.2f * z1;
        float z2 = ac.z + b.z; z2 = z2 > 0.f ? z2 : 0.2f * z2;
        float z3 = ac.w + b.w; z3 = z3 > 0.f ? z3 : 0.2f * z3;
        float part = attr.x * z0 + attr.y * z1 + attr.z * z2 + attr.w * z3;
        part += __shfl_xor_sync(0xffffffffu, part, 1);
        part += __shfl_xor_sync(0xffffffffu, part, 2);
        float ex = __expf(part);
        den += ex;
        acc.x += ac.x * ex; acc.y += ac.y * ex;
        acc.z += ac.z * ex; acc.w += ac.w * ex;
    }

    float inv = 1.f / den;
    int c = lane * 4;
    float o[4];
    o[0] = elu1(acc.x * inv + bias[c + 0]);
    o[1] = elu1(acc.y * inv + bias[c + 1]);
    o[2] = elu1(acc.z * inv + bias[c + 2]);
    o[3] = elu1(acc.w * inv + bias[c + 3]);
    __nv_bfloat16 h[4], l[4];
#pragma unroll
    for (int q = 0; q < 4; q++) split_bf(o[q], h[q], l[q]);
    size_t base = (size_t)w * 128;
    int p0 = permk(c), p1 = permk(c + 2);
    *(uint32_t*)(g_h1h + base + p0) = *(uint32_t*)&h[0];
    *(uint32_t*)(g_h1h + base + p1) = *(uint32_t*)&h[2];
    *(uint32_t*)(g_h1l + base + p0) = *(uint32_t*)&l[0];
    *(uint32_t*)(g_h1l + base + p1) = *(uint32_t*)&l[2];
}

// --------- layer 2 edge pass, CSR, warp per node; writes h2 as permuted bf16 hi/lo ---------
__global__ void k_edge2_csr(const float* __restrict__ att,
                            const float* __restrict__ bias, int N) {
    int gt = blockIdx.x * blockDim.x + threadIdx.x;
    int lane = gt & 31, w = gt >> 5;
    if (w >= N) return;

    float2 attr = *(const float2*)(att + lane * 2);
    float2 b = *(const float2*)(g_xr2 + (size_t)w * 64 + lane * 2);

    int beg = g_rowptr[w], end = g_rowptr[w + 1];
    float2 acc = make_float2(0.f, 0.f);
    float den = 0.f;

    int s = g_esrc[beg];
    float2 a = *(const float2*)(g_xl2 + (size_t)s * 64 + lane * 2);
    for (int p = beg; p < end; p++) {
        float2 ac = a;
        if (p + 1 < end) {
            s = g_esrc[p + 1];
            a = *(const float2*)(g_xl2 + (size_t)s * 64 + lane * 2);
        }
        float z0 = ac.x + b.x; z0 = z0 > 0.f ? z0 : 0.2f * z0;
        float z1 = ac.y + b.y; z1 = z1 > 0.f ? z1 : 0.2f * z1;
        float part = attr.x * z0 + attr.y * z1;
        part += __shfl_xor_sync(0xffffffffu, part, 1);
        part += __shfl_xor_sync(0xffffffffu, part, 2);
        part += __shfl_xor_sync(0xffffffffu, part, 4);
        part += __shfl_xor_sync(0xffffffffu, part, 8);
        part += __shfl_xor_sync(0xffffffffu, part, 16);
        float ex = __expf(part);
        den += ex;
        acc.x += ac.x * ex; acc.y += ac.y * ex;
    }

    float inv = 1.f / den;
    int c = lane * 2;
    float o0 = elu1(acc.x * inv + bias[c + 0]);
    float o1 = elu1(acc.y * inv + bias[c + 1]);
    __nv_bfloat16 h[2], l[2];
    split_bf(o0, h[0], l[0]);
    split_bf(o1, h[1], l[1]);
    size_t base = (size_t)w * 64;
    int p0 = permk(c);
    *(uint32_t*)(g_h2h + base + p0) = *(uint32_t*)&h[0];
    *(uint32_t*)(g_h2l + base + p0) = *(uint32_t*)&l[0];
}

// ------------------------- launch -------------------------
static inline int cdiv(int a, int b) { return (a + b - 1) / b; }

extern "C" void kernel_launch(void* const* d_in, const int* in_sizes, int n_in,
                              void* d_out, int out_size) {
    const float* x     = (const float*)d_in[0];
    const int*   ei    = (const int*)d_in[1];
    const float* Wl1   = (const float*)d_in[2];
    const float* bl1   = (const float*)d_in[3];
    const float* Wr1   = (const float*)d_in[4];
    const float* br1   = (const float*)d_in[5];
    const float* att1  = (const float*)d_in[6];
    const float* bias1 = (const float*)d_in[7];
    const float* Wl2   = (const float*)d_in[8];
    const float* bl2   = (const float*)d_in[9];
    const float* Wr2   = (const float*)d_in[10];
    const float* br2   = (const float*)d_in[11];
    const float* att2  = (const float*)d_in[12];
    const float* bias2 = (const float*)d_in[13];
    const float* Wlin  = (const float*)d_in[14];
    const float* blin  = (const float*)d_in[15];

    int N = in_sizes[0] / 128;
    int E = in_sizes[1] / 2;
    int Etot = E + N;
    int NB = cdiv(N, 256);
    int GW = 224;                              // weight-conversion blocks

    // ---- fork: CSR build runs on side stream, concurrent with cvt + GEMM1 ----
    cudaEventRecord(g_evFork, 0);
    cudaStreamWaitEvent(g_s2, g_evFork, 0);
    k_hist<<<cdiv(E, 256), 256, 0, g_s2>>>(ei, E);
    k_scanblk<<<NB, 256, 0, g_s2>>>(N);
    k_finalize<<<NB, 256, 0, g_s2>>>(N, Etot, NB);
    k_scatter<<<cdiv(E, 256), 256, 0, g_s2>>>(ei, E);
    cudaEventRecord(g_evCsr, g_s2);

    // ---- main chain ----
    k_cvt<<<GW + cdiv(N * 128, 1024), 256>>>(x, N * 128, Wl1, Wr1, Wl2, Wr2, Wlin, GW);

    dim3 g1(cdiv(N, 128), 2);
    k_gemm_bf<128, 128, 0, 0, 1, 1><<<g1, 256>>>(bl1, br1, nullptr, N);

    // join: edge phase needs the CSR
    cudaStreamWaitEvent(0, g_evCsr, 0);
    k_edge1_csr<<<cdiv(N * 32, 256), 256>>>(att1, bias1, N);

    // layer 2
    dim3 g2(cdiv(N, 128), 2);
    k_gemm_bf<128, 64, 0, 1, 2, 2><<<g2, 256>>>(bl2, br2, nullptr, N);
    k_edge2_csr<<<cdiv(N * 32, 256), 256>>>(att2, bias2, N);

    // final linear + ELU -> d_out [N,128]
    dim3 g3(cdiv(N, 128), 1);
    k_gemm_bf<64, 128, 1, 2, 3, 0><<<g3, 256>>>(blin, blin, (float*)d_out, N);
}